// round 9
// baseline (speedup 1.0000x reference)
#include <cuda_runtime.h>
#include <cuda_bf16.h>
#include <cuda_fp16.h>
#include <cstdint>

#define N_VEC    8192
#define K_CODES  16384
#define D_DIM    256
#define MARGIN_D1 7e-4f

// ------------------------- device scratch (globals) -------------------------
__device__ __nv_bfloat16      g_abf[N_VEC * D_DIM];     // z rows, bf16(rn)
__device__ __nv_bfloat16      g_bbf[K_CODES * D_DIM];   // emb rows, bf16(rn)
__device__ float              g_zf [N_VEC * D_DIM];     // z rows, fp32 packed
__device__ float              g_sz [N_VEC];
__device__ unsigned int       g_rowmin[N_VEC];          // bits of min d1 (>0)
__device__ unsigned long long g_best[N_VEC];            // (bits(d)<<32)|k
__device__ __half             g_d1[(size_t)N_VEC * K_CODES]; // rd(d1-1), 256MB
__device__ double             g_loss_part[256];

// ------------------------------ PTX helpers --------------------------------
__device__ __forceinline__ uint32_t smem_u32(const void* p) {
    uint32_t a;
    asm("{ .reg .u64 t; cvta.to.shared.u64 t, %1; cvt.u32.u64 %0, t; }"
        : "=r"(a) : "l"(p));
    return a;
}
__device__ __forceinline__ void ldm_x4(uint32_t* r, uint32_t addr) {
    asm volatile("ldmatrix.sync.aligned.m8n8.x4.shared.b16 {%0,%1,%2,%3}, [%4];"
                 : "=r"(r[0]), "=r"(r[1]), "=r"(r[2]), "=r"(r[3]) : "r"(addr));
}
__device__ __forceinline__ void mma_bf16(float* c, const uint32_t* a,
                                         uint32_t b0, uint32_t b1) {
    asm volatile(
        "mma.sync.aligned.m16n8k16.row.col.f32.bf16.bf16.f32 "
        "{%0,%1,%2,%3}, {%4,%5,%6,%7}, {%8,%9}, {%0,%1,%2,%3};"
        : "+f"(c[0]), "+f"(c[1]), "+f"(c[2]), "+f"(c[3])
        : "r"(a[0]), "r"(a[1]), "r"(a[2]), "r"(a[3]), "r"(b0), "r"(b1));
}
__device__ __forceinline__ void cp16(uint32_t saddr, const void* g) {
    asm volatile("cp.async.cg.shared.global [%0], [%1], 16;"
                 :: "r"(saddr), "l"(g));
}

// ---------------------------------------------------------------------------
__global__ void vq_init_kernel() {
    int i = blockIdx.x * blockDim.x + threadIdx.x;
    if (i < N_VEC) g_rowmin[i] = 0x7F800000u;   // +inf
}

// ---------------------------------------------------------------------------
// pack z -> zf (fp32 row-major), abf (bf16), sz (sequential chain, identical
// order to the R1 kernel that verified rel_err 0.0)
// ---------------------------------------------------------------------------
__global__ void vq_pack_z_kernel(const float* __restrict__ z) {
    int n  = blockIdx.x * blockDim.x + threadIdx.x;
    int b  = n >> 10;
    int hw = n & 1023;
    const float* zp = z + (size_t)b * 262144 + hw;
    float s = 0.f;
#pragma unroll 8
    for (int d = 0; d < D_DIM; d++) {
        float v = zp[(size_t)d * 1024];
        g_zf [n * D_DIM + d] = v;
        g_abf[n * D_DIM + d] = __float2bfloat16_rn(v);
        s = fmaf(v, v, s);
    }
    g_sz[n] = s;
}

__global__ void vq_pack_e_kernel(const float* __restrict__ emb) {
    int i0 = blockIdx.x * 1024 + threadIdx.x;
#pragma unroll
    for (int j = 0; j < 4; j++) {
        int i = i0 + j * 256;
        g_bbf[i] = __float2bfloat16_rn(emb[i]);
    }
}

// ---------------------------------------------------------------------------
// SINGLE-PASS bf16 HMMA GEMM, cp.async 2-stage pipelined mainloop.
// Epilogue (identical numerics to verified R8):
//   - exact fp32 per-row min -> global atomicMin
//   - FULL d1 tile stored as fp16 rd(d1 - 1) via streaming stores (stcs)
// Smem: pipeline buffers (40 KB) unioned with epilogue d1 tile (34.8 KB).
// ---------------------------------------------------------------------------
__global__ __launch_bounds__(256)
void vq_mma_kernel() {
    __shared__ __align__(16) char s_raw[40960];
    // stage s, row r: sA[s*128 + r][.] / sB[...]
    __nv_bfloat16 (*sA)[40] = reinterpret_cast<__nv_bfloat16(*)[40]>(s_raw);
    __nv_bfloat16 (*sB)[40] =
        reinterpret_cast<__nv_bfloat16(*)[40]>(s_raw + 20480);
    __half (*s_d1)[136] = reinterpret_cast<__half(*)[136]>(s_raw);

    const int tid  = threadIdx.x;
    const int lane = tid & 31;
    const int wid  = tid >> 5;
    const int wm   = wid >> 1;               // 0..3
    const int wn   = wid & 1;                // 0..1
    const int n0   = blockIdx.x * 128;       // z-row base
    const int k0   = blockIdx.y * 128;       // code base

    float acc[2][8][4];
#pragma unroll
    for (int mi = 0; mi < 2; mi++)
#pragma unroll
        for (int ni = 0; ni < 8; ni++)
#pragma unroll
            for (int r = 0; r < 4; r++) acc[mi][ni][r] = 0.f;

    const int lrow = tid >> 2;        // 0..63
    const int lq   = (tid & 3) * 8;   // bf16 col of 16B chunk

    // prologue: stage 0
    {
#pragma unroll
        for (int j = 0; j < 2; j++) {
            int row = lrow + j * 64;
            cp16(smem_u32(&sA[row][lq]),
                 &g_abf[(size_t)(n0 + row) * D_DIM + lq]);
            cp16(smem_u32(&sB[row][lq]),
                 &g_bbf[(size_t)(k0 + row) * D_DIM + lq]);
        }
        asm volatile("cp.async.commit_group;");
    }

    for (int kc = 0; kc < 8; kc++) {
        const int buf = (kc & 1) * 128;
        if (kc < 7) {
            const int nb = ((kc + 1) & 1) * 128;
            const int kb = (kc + 1) * 32;
#pragma unroll
            for (int j = 0; j < 2; j++) {
                int row = lrow + j * 64;
                cp16(smem_u32(&sA[nb + row][lq]),
                     &g_abf[(size_t)(n0 + row) * D_DIM + kb + lq]);
                cp16(smem_u32(&sB[nb + row][lq]),
                     &g_bbf[(size_t)(k0 + row) * D_DIM + kb + lq]);
            }
            asm volatile("cp.async.commit_group;");
            asm volatile("cp.async.wait_group 1;");
        } else {
            asm volatile("cp.async.wait_group 0;");
        }
        __syncthreads();

#pragma unroll
        for (int ks = 0; ks < 2; ks++) {
            uint32_t a[2][4];
#pragma unroll
            for (int mi = 0; mi < 2; mi++) {
                int r = wm * 32 + mi * 16 + (lane & 15);
                int c = ks * 16 + (lane >> 4) * 8;
                ldm_x4(a[mi], smem_u32(&sA[buf + r][c]));
            }
            uint32_t b[4][4];
#pragma unroll
            for (int g = 0; g < 4; g++) {
                int r = wn * 64 + g * 16 + (lane & 15);
                int c = ks * 16 + (lane >> 4) * 8;
                ldm_x4(b[g], smem_u32(&sB[buf + r][c]));
            }
#pragma unroll
            for (int mi = 0; mi < 2; mi++)
#pragma unroll
                for (int g = 0; g < 4; g++) {
                    mma_bf16(acc[mi][2 * g],     a[mi], b[g][0], b[g][2]);
                    mma_bf16(acc[mi][2 * g + 1], a[mi], b[g][1], b[g][3]);
                }
        }
        __syncthreads();   // protect buffer before next cp.async overwrites
    }

    // ---- epilogue: d1 tile -> smem (fp16 rd), exact fp32 rowmin ----
    // (pipeline buffers are dead; s_d1 overlays them — last barrier above)
#pragma unroll
    for (int mi = 0; mi < 2; mi++)
#pragma unroll
        for (int ci = 0; ci < 2; ci++) {
            int rl = wm * 32 + mi * 16 + ci * 8 + (lane >> 2);
            float mn = 3.402823466e+38f;
#pragma unroll
            for (int ni = 0; ni < 8; ni++) {
                float d0 = __fmaf_rn(-2.0f, acc[mi][ni][2 * ci],     1.0f);
                float d1 = __fmaf_rn(-2.0f, acc[mi][ni][2 * ci + 1], 1.0f);
                int col = wn * 64 + ni * 8 + (lane & 3) * 2;
                __half2 h = __halves2half2(
                    __float2half_rd(__fsub_rn(d0, 1.0f)),
                    __float2half_rd(__fsub_rn(d1, 1.0f)));
                *reinterpret_cast<__half2*>(&s_d1[rl][col]) = h;
                mn = fminf(mn, fminf(d0, d1));
            }
            mn = fminf(mn, __shfl_xor_sync(0xFFFFFFFFu, mn, 1));
            mn = fminf(mn, __shfl_xor_sync(0xFFFFFFFFu, mn, 2));
            if ((lane & 3) == 0)
                atomicMin(&g_rowmin[n0 + rl], __float_as_uint(mn));
        }
    __syncthreads();

    // coalesced streaming store of the 128x128 fp16 tile (evict-first in L2)
#pragma unroll
    for (int i = 0; i < 8; i++) {
        int idx = i * 256 + tid;             // 0..2047 (uint4 units)
        int row = idx >> 4;
        int col = (idx & 15) * 8;
        float4 v = *reinterpret_cast<float4*>(&s_d1[row][col]);
        __stcs(reinterpret_cast<float4*>(
            &g_d1[(size_t)(n0 + row) * K_CODES + k0 + col]), v);
    }
}

// ---------------------------------------------------------------------------
// Fused scan + exact rescore: one 128-thread block per z-row (verified R8).
// ---------------------------------------------------------------------------
__global__ __launch_bounds__(128)
void vq_scan_rescore_kernel(const float* __restrict__ emb) {
    __shared__ float s_z[D_DIM];
    __shared__ int   s_list[256];
    __shared__ int   s_cnt;
    __shared__ unsigned long long s_best;

    const int n   = blockIdx.x;
    const int tid = threadIdx.x;

    if (tid == 0) { s_cnt = 0; s_best = 0xFFFFFFFFFFFFFFFFULL; }
    s_z[tid]       = g_zf[(size_t)n * D_DIM + tid];
    s_z[tid + 128] = g_zf[(size_t)n * D_DIM + tid + 128];
    const float thr = __uint_as_float(g_rowmin[n]) - 1.0f + MARGIN_D1;
    __syncthreads();

    const uint4* rowp = reinterpret_cast<const uint4*>(
        &g_d1[(size_t)n * K_CODES]);
#pragma unroll
    for (int j = 0; j < 16; j++) {
        int u = j * 128 + tid;               // uint4 index: 8 halves
        uint4 v = __ldcs(&rowp[u]);
        const uint32_t w[4] = {v.x, v.y, v.z, v.w};
#pragma unroll
        for (int q = 0; q < 4; q++) {
            __half2 p = *reinterpret_cast<const __half2*>(&w[q]);
            float lo = __low2float(p);
            float hi = __high2float(p);
            if (lo <= thr) {
                int pos = atomicAdd(&s_cnt, 1);
                if (pos < 256) s_list[pos] = u * 8 + q * 2;
            }
            if (hi <= thr) {
                int pos = atomicAdd(&s_cnt, 1);
                if (pos < 256) s_list[pos] = u * 8 + q * 2 + 1;
            }
        }
    }
    __syncthreads();

    int cnt = s_cnt < 256 ? s_cnt : 256;
    float sz = g_sz[n];
    for (int c = tid; c < cnt; c += 128) {
        int k = s_list[c];
        const float* er = emb + (size_t)k * D_DIM;
        float acc = 0.f;
#pragma unroll 8
        for (int d = 0; d < D_DIM; d++)
            acc = fmaf(s_z[d], er[d], acc);
        float dval = __fsub_rn(sz, __fmul_rn(2.0f, acc));
        unsigned long long key =
            ((unsigned long long)__float_as_uint(dval) << 32) | (unsigned int)k;
        atomicMin(&s_best, key);
    }
    __syncthreads();
    if (tid == 0) g_best[n] = s_best;
}

// ---------------------------------------------------------------------------
// finalize: 256 blocks = (32 n-groups) x (8 d-chunks); verified R1 math.
// ---------------------------------------------------------------------------
__global__ void vq_finalize_kernel(const float* __restrict__ z,
                                   const float* __restrict__ emb,
                                   float* __restrict__ out, int out_size) {
    __shared__ double sred[256];
    int ng = blockIdx.x >> 3;
    int dc = blockIdx.x & 7;
    int n  = ng * 256 + threadIdx.x;
    int b  = n >> 10;
    int hw = n & 1023;

    int k = (int)(unsigned int)(g_best[n] & 0xFFFFFFFFu);

    const float* e  = emb + (size_t)k * D_DIM;
    const float* zp = z   + (size_t)b * 262144 + hw;
    float*       op = out + (size_t)b * 262144 + hw;

    double lsum = 0.0;
#pragma unroll 8
    for (int d = dc * 32; d < dc * 32 + 32; d++) {
        float zv   = zp[(size_t)d * 1024];
        float ev   = e[d];
        float diff = __fsub_rn(ev, zv);          // fl(z_q - z)
        float q    = __fadd_rn(zv, diff);        // fl(z + fl(z_q - z))
        op[(size_t)d * 1024] = q;
        lsum += (double)diff * (double)diff;
    }

    if (dc == 0) {
        int idx_pos = 2097152 + 1 + n;
        if (idx_pos < out_size) out[idx_pos] = (float)k;
    }

    sred[threadIdx.x] = lsum;
    __syncthreads();
    for (int s = 128; s > 0; s >>= 1) {
        if (threadIdx.x < s) sred[threadIdx.x] += sred[threadIdx.x + s];
        __syncthreads();
    }
    if (threadIdx.x == 0) g_loss_part[blockIdx.x] = sred[0];
}

__global__ void vq_loss_kernel(float* __restrict__ out, int out_size) {
    if (threadIdx.x == 0 && blockIdx.x == 0) {
        double s = 0.0;
        for (int i = 0; i < 256; i++) s += g_loss_part[i];
        double mean = s / 2097152.0;
        if (2097152 < out_size) out[2097152] = (float)(mean * 1.25);
    }
}

// ---------------------------------------------------------------------------
extern "C" void kernel_launch(void* const* d_in, const int* in_sizes, int n_in,
                              void* d_out, int out_size) {
    const float* z   = (const float*)d_in[0];   // [8,256,32,32]
    const float* emb = (const float*)d_in[1];   // [16384,256]
    float* out = (float*)d_out;

    vq_init_kernel<<<32, 256>>>();
    vq_pack_z_kernel<<<32, 256>>>(z);
    vq_pack_e_kernel<<<4096, 256>>>(emb);

    dim3 grid(N_VEC / 128, K_CODES / 128);     // 64 x 128 = 8192 blocks
    vq_mma_kernel<<<grid, 256>>>();

    vq_scan_rescore_kernel<<<N_VEC, 128>>>(emb);
    vq_finalize_kernel<<<256, 256>>>(z, emb, out, out_size);
    vq_loss_kernel<<<1, 32>>>(out, out_size);
}

// round 10
// speedup vs baseline: 1.3710x; 1.3710x over previous
#include <cuda_runtime.h>
#include <cuda_bf16.h>
#include <cuda_fp16.h>
#include <cstdint>

#define N_VEC    8192
#define K_CODES  16384
#define D_DIM    256
#define MARGIN_D1 7e-4f

// ------------------------- device scratch (globals) -------------------------
__device__ __nv_bfloat16      g_abf[N_VEC * D_DIM];     // z rows, bf16(rn)
__device__ __nv_bfloat16      g_bbf[K_CODES * D_DIM];   // emb rows, bf16(rn)
__device__ float              g_zf [N_VEC * D_DIM];     // z rows, fp32 packed
__device__ float              g_sz [N_VEC];
__device__ unsigned int       g_rowmin[N_VEC];          // bits of min d1 (>0)
__device__ unsigned long long g_best[N_VEC];            // (bits(d)<<32)|k
__device__ __half             g_d1[(size_t)N_VEC * K_CODES]; // rd(d1-1), 256MB
__device__ double             g_loss_part[256];

// ------------------------------ PTX helpers --------------------------------
__device__ __forceinline__ uint32_t smem_u32(const void* p) {
    uint32_t a;
    asm("{ .reg .u64 t; cvta.to.shared.u64 t, %1; cvt.u32.u64 %0, t; }"
        : "=r"(a) : "l"(p));
    return a;
}
__device__ __forceinline__ void ldm_x4(uint32_t* r, uint32_t addr) {
    asm volatile("ldmatrix.sync.aligned.m8n8.x4.shared.b16 {%0,%1,%2,%3}, [%4];"
                 : "=r"(r[0]), "=r"(r[1]), "=r"(r[2]), "=r"(r[3]) : "r"(addr));
}
__device__ __forceinline__ void mma_bf16(float* c, const uint32_t* a,
                                         uint32_t b0, uint32_t b1) {
    asm volatile(
        "mma.sync.aligned.m16n8k16.row.col.f32.bf16.bf16.f32 "
        "{%0,%1,%2,%3}, {%4,%5,%6,%7}, {%8,%9}, {%0,%1,%2,%3};"
        : "+f"(c[0]), "+f"(c[1]), "+f"(c[2]), "+f"(c[3])
        : "r"(a[0]), "r"(a[1]), "r"(a[2]), "r"(a[3]), "r"(b0), "r"(b1));
}

// ---------------------------------------------------------------------------
__global__ void vq_init_kernel() {
    int i = blockIdx.x * blockDim.x + threadIdx.x;
    if (i < N_VEC) g_rowmin[i] = 0x7F800000u;   // +inf
}

// ---------------------------------------------------------------------------
// pack z -> zf (fp32 row-major), abf (bf16), sz (sequential chain, identical
// order to the R1 kernel that verified rel_err 0.0)
// ---------------------------------------------------------------------------
__global__ void vq_pack_z_kernel(const float* __restrict__ z) {
    int n  = blockIdx.x * blockDim.x + threadIdx.x;
    int b  = n >> 10;
    int hw = n & 1023;
    const float* zp = z + (size_t)b * 262144 + hw;
    float s = 0.f;
#pragma unroll 8
    for (int d = 0; d < D_DIM; d++) {
        float v = zp[(size_t)d * 1024];
        g_zf [n * D_DIM + d] = v;
        g_abf[n * D_DIM + d] = __float2bfloat16_rn(v);
        s = fmaf(v, v, s);
    }
    g_sz[n] = s;
}

__global__ void vq_pack_e_kernel(const float* __restrict__ emb) {
    int i0 = blockIdx.x * 1024 + threadIdx.x;
#pragma unroll
    for (int j = 0; j < 4; j++) {
        int i = i0 + j * 256;
        g_bbf[i] = __float2bfloat16_rn(emb[i]);
    }
}

// ---------------------------------------------------------------------------
// SINGLE-PASS bf16 HMMA GEMM, block tile 256x128, 8 warps = 4m x 2n of 64x64.
// 0.25 LDSM per MMA (was 0.75).  Register-prefetch double buffering of the
// global loads.  Epilogue: exact fp32 rowmin + full d1 dump (fp16 rd, stcs),
// numerics identical to verified R8, done in two 128-row phases.
// ---------------------------------------------------------------------------
__global__ __launch_bounds__(256, 1)
void vq_mma_kernel() {
    __shared__ __align__(16) char s_raw[35840];
    __nv_bfloat16 (*sA)[40] = reinterpret_cast<__nv_bfloat16(*)[40]>(s_raw);
    __nv_bfloat16 (*sB)[40] =
        reinterpret_cast<__nv_bfloat16(*)[40]>(s_raw + 20480);
    __half (*s_d1)[136] = reinterpret_cast<__half(*)[136]>(s_raw);

    const int tid  = threadIdx.x;
    const int lane = tid & 31;
    const int wid  = tid >> 5;
    const int wm   = wid >> 1;               // 0..3  (64-row m tile)
    const int wn   = wid & 1;                // 0..1  (64-col n tile)
    const int n0   = blockIdx.x * 256;       // z-row base
    const int k0   = blockIdx.y * 128;       // code base

    float acc[4][8][4];
#pragma unroll
    for (int mi = 0; mi < 4; mi++)
#pragma unroll
        for (int ni = 0; ni < 8; ni++)
#pragma unroll
            for (int r = 0; r < 4; r++) acc[mi][ni][r] = 0.f;

    // global-load ownership: A chunk j: linear c = j*256+tid -> row c>>2,
    // col8 = (c&3)*8 ; B chunk j (j<2): same with 128 rows
    uint4 pa[4], pb[2];
    {
#pragma unroll
        for (int j = 0; j < 4; j++) {
            int c = j * 256 + tid;
            pa[j] = *reinterpret_cast<const uint4*>(
                &g_abf[(size_t)(n0 + (c >> 2)) * D_DIM + (c & 3) * 8]);
        }
#pragma unroll
        for (int j = 0; j < 2; j++) {
            int c = j * 256 + tid;
            pb[j] = *reinterpret_cast<const uint4*>(
                &g_bbf[(size_t)(k0 + (c >> 2)) * D_DIM + (c & 3) * 8]);
        }
    }

    for (int kc = 0; kc < 8; kc++) {
        __syncthreads();   // previous compute done before overwriting smem
#pragma unroll
        for (int j = 0; j < 4; j++) {
            int c = j * 256 + tid;
            *reinterpret_cast<uint4*>(&sA[c >> 2][(c & 3) * 8]) = pa[j];
        }
#pragma unroll
        for (int j = 0; j < 2; j++) {
            int c = j * 256 + tid;
            *reinterpret_cast<uint4*>(&sB[c >> 2][(c & 3) * 8]) = pb[j];
        }
        __syncthreads();

        if (kc < 7) {      // prefetch next chunk; LDG overlaps compute below
            const int kb = (kc + 1) * 32;
#pragma unroll
            for (int j = 0; j < 4; j++) {
                int c = j * 256 + tid;
                pa[j] = *reinterpret_cast<const uint4*>(
                    &g_abf[(size_t)(n0 + (c >> 2)) * D_DIM + kb + (c & 3) * 8]);
            }
#pragma unroll
            for (int j = 0; j < 2; j++) {
                int c = j * 256 + tid;
                pb[j] = *reinterpret_cast<const uint4*>(
                    &g_bbf[(size_t)(k0 + (c >> 2)) * D_DIM + kb + (c & 3) * 8]);
            }
        }

#pragma unroll
        for (int ks = 0; ks < 2; ks++) {
            uint32_t a[4][4];
#pragma unroll
            for (int mi = 0; mi < 4; mi++) {
                int r = wm * 64 + mi * 16 + (lane & 15);
                int c = ks * 16 + (lane >> 4) * 8;
                ldm_x4(a[mi], smem_u32(&sA[r][c]));
            }
            uint32_t b[4][4];
#pragma unroll
            for (int g = 0; g < 4; g++) {
                int r = wn * 64 + g * 16 + (lane & 15);
                int c = ks * 16 + (lane >> 4) * 8;
                ldm_x4(b[g], smem_u32(&sB[r][c]));
            }
#pragma unroll
            for (int mi = 0; mi < 4; mi++)
#pragma unroll
                for (int g = 0; g < 4; g++) {
                    mma_bf16(acc[mi][2 * g],     a[mi], b[g][0], b[g][2]);
                    mma_bf16(acc[mi][2 * g + 1], a[mi], b[g][1], b[g][3]);
                }
        }
    }

    // ---- epilogue: two 128-row phases; numerics identical to R8 ----
#pragma unroll
    for (int p = 0; p < 2; p++) {
        __syncthreads();   // smem buffers (or previous phase) fully consumed
        if ((wm >> 1) == p) {
            const int wml = wm & 1;   // 0..1 within phase
#pragma unroll
            for (int mi = 0; mi < 4; mi++)
#pragma unroll
                for (int ci = 0; ci < 2; ci++) {
                    int rl = wml * 64 + mi * 16 + ci * 8 + (lane >> 2);
                    float mn = 3.402823466e+38f;
#pragma unroll
                    for (int ni = 0; ni < 8; ni++) {
                        float d0 = __fmaf_rn(-2.0f, acc[mi][ni][2 * ci],     1.0f);
                        float d1 = __fmaf_rn(-2.0f, acc[mi][ni][2 * ci + 1], 1.0f);
                        int col = wn * 64 + ni * 8 + (lane & 3) * 2;
                        __half2 h = __halves2half2(
                            __float2half_rd(__fsub_rn(d0, 1.0f)),
                            __float2half_rd(__fsub_rn(d1, 1.0f)));
                        *reinterpret_cast<__half2*>(&s_d1[rl][col]) = h;
                        mn = fminf(mn, fminf(d0, d1));
                    }
                    mn = fminf(mn, __shfl_xor_sync(0xFFFFFFFFu, mn, 1));
                    mn = fminf(mn, __shfl_xor_sync(0xFFFFFFFFu, mn, 2));
                    if ((lane & 3) == 0)
                        atomicMin(&g_rowmin[n0 + p * 128 + rl],
                                  __float_as_uint(mn));
                }
        }
        __syncthreads();

        // coalesced streaming store of this 128x128 fp16 tile
#pragma unroll
        for (int i = 0; i < 8; i++) {
            int idx = i * 256 + tid;
            int row = idx >> 4;
            int col = (idx & 15) * 8;
            float4 v = *reinterpret_cast<float4*>(&s_d1[row][col]);
            __stcs(reinterpret_cast<float4*>(
                &g_d1[(size_t)(n0 + p * 128 + row) * K_CODES + k0 + col]), v);
        }
    }
}

// ---------------------------------------------------------------------------
// Fused scan + exact rescore: one 128-thread block per z-row (verified R8).
// ---------------------------------------------------------------------------
__global__ __launch_bounds__(128)
void vq_scan_rescore_kernel(const float* __restrict__ emb) {
    __shared__ float s_z[D_DIM];
    __shared__ int   s_list[256];
    __shared__ int   s_cnt;
    __shared__ unsigned long long s_best;

    const int n   = blockIdx.x;
    const int tid = threadIdx.x;

    if (tid == 0) { s_cnt = 0; s_best = 0xFFFFFFFFFFFFFFFFULL; }
    s_z[tid]       = g_zf[(size_t)n * D_DIM + tid];
    s_z[tid + 128] = g_zf[(size_t)n * D_DIM + tid + 128];
    const float thr = __uint_as_float(g_rowmin[n]) - 1.0f + MARGIN_D1;
    __syncthreads();

    const uint4* rowp = reinterpret_cast<const uint4*>(
        &g_d1[(size_t)n * K_CODES]);
#pragma unroll
    for (int j = 0; j < 16; j++) {
        int u = j * 128 + tid;               // uint4 index: 8 halves
        uint4 v = __ldcs(&rowp[u]);
        const uint32_t w[4] = {v.x, v.y, v.z, v.w};
#pragma unroll
        for (int q = 0; q < 4; q++) {
            __half2 p = *reinterpret_cast<const __half2*>(&w[q]);
            float lo = __low2float(p);
            float hi = __high2float(p);
            if (lo <= thr) {
                int pos = atomicAdd(&s_cnt, 1);
                if (pos < 256) s_list[pos] = u * 8 + q * 2;
            }
            if (hi <= thr) {
                int pos = atomicAdd(&s_cnt, 1);
                if (pos < 256) s_list[pos] = u * 8 + q * 2 + 1;
            }
        }
    }
    __syncthreads();

    int cnt = s_cnt < 256 ? s_cnt : 256;
    float sz = g_sz[n];
    for (int c = tid; c < cnt; c += 128) {
        int k = s_list[c];
        const float* er = emb + (size_t)k * D_DIM;
        float acc = 0.f;
#pragma unroll 8
        for (int d = 0; d < D_DIM; d++)
            acc = fmaf(s_z[d], er[d], acc);
        float dval = __fsub_rn(sz, __fmul_rn(2.0f, acc));
        unsigned long long key =
            ((unsigned long long)__float_as_uint(dval) << 32) | (unsigned int)k;
        atomicMin(&s_best, key);
    }
    __syncthreads();
    if (tid == 0) g_best[n] = s_best;
}

// ---------------------------------------------------------------------------
// finalize: 256 blocks = (32 n-groups) x (8 d-chunks); verified R1 math.
// ---------------------------------------------------------------------------
__global__ void vq_finalize_kernel(const float* __restrict__ z,
                                   const float* __restrict__ emb,
                                   float* __restrict__ out, int out_size) {
    __shared__ double sred[256];
    int ng = blockIdx.x >> 3;
    int dc = blockIdx.x & 7;
    int n  = ng * 256 + threadIdx.x;
    int b  = n >> 10;
    int hw = n & 1023;

    int k = (int)(unsigned int)(g_best[n] & 0xFFFFFFFFu);

    const float* e  = emb + (size_t)k * D_DIM;
    const float* zp = z   + (size_t)b * 262144 + hw;
    float*       op = out + (size_t)b * 262144 + hw;

    double lsum = 0.0;
#pragma unroll 8
    for (int d = dc * 32; d < dc * 32 + 32; d++) {
        float zv   = zp[(size_t)d * 1024];
        float ev   = e[d];
        float diff = __fsub_rn(ev, zv);          // fl(z_q - z)
        float q    = __fadd_rn(zv, diff);        // fl(z + fl(z_q - z))
        op[(size_t)d * 1024] = q;
        lsum += (double)diff * (double)diff;
    }

    if (dc == 0) {
        int idx_pos = 2097152 + 1 + n;
        if (idx_pos < out_size) out[idx_pos] = (float)k;
    }

    sred[threadIdx.x] = lsum;
    __syncthreads();
    for (int s = 128; s > 0; s >>= 1) {
        if (threadIdx.x < s) sred[threadIdx.x] += sred[threadIdx.x + s];
        __syncthreads();
    }
    if (threadIdx.x == 0) g_loss_part[blockIdx.x] = sred[0];
}

__global__ void vq_loss_kernel(float* __restrict__ out, int out_size) {
    if (threadIdx.x == 0 && blockIdx.x == 0) {
        double s = 0.0;
        for (int i = 0; i < 256; i++) s += g_loss_part[i];
        double mean = s / 2097152.0;
        if (2097152 < out_size) out[2097152] = (float)(mean * 1.25);
    }
}

// ---------------------------------------------------------------------------
extern "C" void kernel_launch(void* const* d_in, const int* in_sizes, int n_in,
                              void* d_out, int out_size) {
    const float* z   = (const float*)d_in[0];   // [8,256,32,32]
    const float* emb = (const float*)d_in[1];   // [16384,256]
    float* out = (float*)d_out;

    vq_init_kernel<<<32, 256>>>();
    vq_pack_z_kernel<<<32, 256>>>(z);
    vq_pack_e_kernel<<<4096, 256>>>(emb);

    dim3 grid(N_VEC / 256, K_CODES / 128);     // 32 x 128 = 4096 blocks
    vq_mma_kernel<<<grid, 256>>>();

    vq_scan_rescore_kernel<<<N_VEC, 128>>>(emb);
    vq_finalize_kernel<<<256, 256>>>(z, emb, out, out_size);
    vq_loss_kernel<<<1, 32>>>(out, out_size);
}

// round 11
// speedup vs baseline: 1.5513x; 1.1315x over previous
#include <cuda_runtime.h>
#include <cuda_bf16.h>
#include <cuda_fp16.h>
#include <cstdint>

#define N_VEC    8192
#define K_CODES  16384
#define D_DIM    256
#define MARGIN_D1 7e-4f

// ------------------------- device scratch (globals) -------------------------
__device__ __nv_bfloat16      g_abf[N_VEC * D_DIM];     // z rows, bf16(rn)
__device__ __nv_bfloat16      g_bbf[K_CODES * D_DIM];   // emb rows, bf16(rn)
__device__ float              g_zf [N_VEC * D_DIM];     // z rows, fp32 packed
__device__ float              g_sz [N_VEC];
__device__ unsigned int       g_rowmin[N_VEC];          // bits of min d1 (>0)
__device__ unsigned long long g_best[N_VEC];            // (bits(d)<<32)|k
__device__ __half             g_d1[(size_t)N_VEC * K_CODES]; // rd(d1-1), 256MB
__device__ double             g_loss_part[256];

// ------------------------------ PTX helpers --------------------------------
__device__ __forceinline__ uint32_t smem_u32(const void* p) {
    uint32_t a;
    asm("{ .reg .u64 t; cvta.to.shared.u64 t, %1; cvt.u32.u64 %0, t; }"
        : "=r"(a) : "l"(p));
    return a;
}
__device__ __forceinline__ void ldm_x4(uint32_t* r, uint32_t addr) {
    asm volatile("ldmatrix.sync.aligned.m8n8.x4.shared.b16 {%0,%1,%2,%3}, [%4];"
                 : "=r"(r[0]), "=r"(r[1]), "=r"(r[2]), "=r"(r[3]) : "r"(addr));
}
__device__ __forceinline__ void mma_bf16(float* c, const uint32_t* a,
                                         uint32_t b0, uint32_t b1) {
    asm volatile(
        "mma.sync.aligned.m16n8k16.row.col.f32.bf16.bf16.f32 "
        "{%0,%1,%2,%3}, {%4,%5,%6,%7}, {%8,%9}, {%0,%1,%2,%3};"
        : "+f"(c[0]), "+f"(c[1]), "+f"(c[2]), "+f"(c[3])
        : "r"(a[0]), "r"(a[1]), "r"(a[2]), "r"(a[3]), "r"(b0), "r"(b1));
}

// ---------------------------------------------------------------------------
__global__ void vq_init_kernel() {
    int i = blockIdx.x * blockDim.x + threadIdx.x;
    if (i < N_VEC) g_rowmin[i] = 0x7F800000u;   // +inf
}

// ---------------------------------------------------------------------------
// pack z -> zf (fp32 row-major), abf (bf16), sz (sequential chain, identical
// order to the R1 kernel that verified rel_err 0.0)
// ---------------------------------------------------------------------------
__global__ void vq_pack_z_kernel(const float* __restrict__ z) {
    int n  = blockIdx.x * blockDim.x + threadIdx.x;
    int b  = n >> 10;
    int hw = n & 1023;
    const float* zp = z + (size_t)b * 262144 + hw;
    float s = 0.f;
#pragma unroll 8
    for (int d = 0; d < D_DIM; d++) {
        float v = zp[(size_t)d * 1024];
        g_zf [n * D_DIM + d] = v;
        g_abf[n * D_DIM + d] = __float2bfloat16_rn(v);
        s = fmaf(v, v, s);
    }
    g_sz[n] = s;
}

__global__ void vq_pack_e_kernel(const float* __restrict__ emb) {
    int i0 = blockIdx.x * 1024 + threadIdx.x;
#pragma unroll
    for (int j = 0; j < 4; j++) {
        int i = i0 + j * 256;
        g_bbf[i] = __float2bfloat16_rn(emb[i]);
    }
}

// ---------------------------------------------------------------------------
// SINGLE-PASS bf16 HMMA GEMM — R8 tile (128x128, 8 warps of 32x64, 2 blk/SM)
// with a register-prefetch software pipeline: LDG for chunk kc+1 is issued
// BEFORE the compute of chunk kc, so global latency overlaps the MMAs.
// Epilogue identical to verified R8: exact fp32 rowmin (atomicMin) + full d1
// tile as fp16 rd(d1 - 1) streamed out with stcs.
// ---------------------------------------------------------------------------
__global__ __launch_bounds__(256, 2)
void vq_mma_kernel() {
    __shared__ __align__(16) __nv_bfloat16 sA[128][40];
    __shared__ __align__(16) __nv_bfloat16 sB[128][40];
    __shared__ __align__(16) __half s_d1[128][136];

    const int tid  = threadIdx.x;
    const int lane = tid & 31;
    const int wid  = tid >> 5;
    const int wm   = wid >> 1;               // 0..3
    const int wn   = wid & 1;                // 0..1
    const int n0   = blockIdx.x * 128;       // z-row base
    const int k0   = blockIdx.y * 128;       // code base

    float acc[2][8][4];
#pragma unroll
    for (int mi = 0; mi < 2; mi++)
#pragma unroll
        for (int ni = 0; ni < 8; ni++)
#pragma unroll
            for (int r = 0; r < 4; r++) acc[mi][ni][r] = 0.f;

    const int lrow = tid >> 2;        // 0..63 (owns rows lrow, lrow+64)
    const int lq   = (tid & 3) * 8;   // bf16 col of 16B chunk

    const __nv_bfloat16* ap0 = &g_abf[(size_t)(n0 + lrow) * D_DIM + lq];
    const __nv_bfloat16* ap1 = ap0 + (size_t)64 * D_DIM;
    const __nv_bfloat16* bp0 = &g_bbf[(size_t)(k0 + lrow) * D_DIM + lq];
    const __nv_bfloat16* bp1 = bp0 + (size_t)64 * D_DIM;

    // prefetch chunk 0
    uint4 pa0 = *reinterpret_cast<const uint4*>(ap0);
    uint4 pa1 = *reinterpret_cast<const uint4*>(ap1);
    uint4 pb0 = *reinterpret_cast<const uint4*>(bp0);
    uint4 pb1 = *reinterpret_cast<const uint4*>(bp1);

    for (int kc = 0; kc < 8; kc++) {
        __syncthreads();   // previous chunk's readers done
        *reinterpret_cast<uint4*>(&sA[lrow     ][lq]) = pa0;
        *reinterpret_cast<uint4*>(&sA[lrow + 64][lq]) = pa1;
        *reinterpret_cast<uint4*>(&sB[lrow     ][lq]) = pb0;
        *reinterpret_cast<uint4*>(&sB[lrow + 64][lq]) = pb1;
        __syncthreads();

        if (kc < 7) {      // prefetch next chunk; latency overlaps compute
            const int kb = (kc + 1) * 32;
            pa0 = *reinterpret_cast<const uint4*>(ap0 + kb);
            pa1 = *reinterpret_cast<const uint4*>(ap1 + kb);
            pb0 = *reinterpret_cast<const uint4*>(bp0 + kb);
            pb1 = *reinterpret_cast<const uint4*>(bp1 + kb);
        }

#pragma unroll
        for (int ks = 0; ks < 2; ks++) {
            uint32_t a[2][4];
#pragma unroll
            for (int mi = 0; mi < 2; mi++) {
                int r = wm * 32 + mi * 16 + (lane & 15);
                int c = ks * 16 + (lane >> 4) * 8;
                ldm_x4(a[mi], smem_u32(&sA[r][c]));
            }
            uint32_t b[4][4];
#pragma unroll
            for (int g = 0; g < 4; g++) {
                int r = wn * 64 + g * 16 + (lane & 15);
                int c = ks * 16 + (lane >> 4) * 8;
                ldm_x4(b[g], smem_u32(&sB[r][c]));
            }
#pragma unroll
            for (int mi = 0; mi < 2; mi++)
#pragma unroll
                for (int g = 0; g < 4; g++) {
                    mma_bf16(acc[mi][2 * g],     a[mi], b[g][0], b[g][2]);
                    mma_bf16(acc[mi][2 * g + 1], a[mi], b[g][1], b[g][3]);
                }
        }
    }

    // ---- epilogue: d1 tile -> smem (fp16 rd), exact fp32 rowmin ----
#pragma unroll
    for (int mi = 0; mi < 2; mi++)
#pragma unroll
        for (int ci = 0; ci < 2; ci++) {
            int rl = wm * 32 + mi * 16 + ci * 8 + (lane >> 2);
            float mn = 3.402823466e+38f;
#pragma unroll
            for (int ni = 0; ni < 8; ni++) {
                float d0 = __fmaf_rn(-2.0f, acc[mi][ni][2 * ci],     1.0f);
                float d1 = __fmaf_rn(-2.0f, acc[mi][ni][2 * ci + 1], 1.0f);
                int col = wn * 64 + ni * 8 + (lane & 3) * 2;
                __half2 h = __halves2half2(
                    __float2half_rd(__fsub_rn(d0, 1.0f)),
                    __float2half_rd(__fsub_rn(d1, 1.0f)));
                *reinterpret_cast<__half2*>(&s_d1[rl][col]) = h;
                mn = fminf(mn, fminf(d0, d1));
            }
            mn = fminf(mn, __shfl_xor_sync(0xFFFFFFFFu, mn, 1));
            mn = fminf(mn, __shfl_xor_sync(0xFFFFFFFFu, mn, 2));
            if ((lane & 3) == 0)
                atomicMin(&g_rowmin[n0 + rl], __float_as_uint(mn));
        }
    __syncthreads();

    // coalesced streaming store of the 128x128 fp16 tile (evict-first in L2)
#pragma unroll
    for (int i = 0; i < 8; i++) {
        int idx = i * 256 + tid;             // 0..2047 (uint4 units)
        int row = idx >> 4;
        int col = (idx & 15) * 8;
        float4 v = *reinterpret_cast<float4*>(&s_d1[row][col]);
        __stcs(reinterpret_cast<float4*>(
            &g_d1[(size_t)(n0 + row) * K_CODES + k0 + col]), v);
    }
}

// ---------------------------------------------------------------------------
// Fused scan + exact rescore: one 128-thread block per z-row (verified R8).
// ---------------------------------------------------------------------------
__global__ __launch_bounds__(128)
void vq_scan_rescore_kernel(const float* __restrict__ emb) {
    __shared__ float s_z[D_DIM];
    __shared__ int   s_list[256];
    __shared__ int   s_cnt;
    __shared__ unsigned long long s_best;

    const int n   = blockIdx.x;
    const int tid = threadIdx.x;

    if (tid == 0) { s_cnt = 0; s_best = 0xFFFFFFFFFFFFFFFFULL; }
    s_z[tid]       = g_zf[(size_t)n * D_DIM + tid];
    s_z[tid + 128] = g_zf[(size_t)n * D_DIM + tid + 128];
    const float thr = __uint_as_float(g_rowmin[n]) - 1.0f + MARGIN_D1;
    __syncthreads();

    const uint4* rowp = reinterpret_cast<const uint4*>(
        &g_d1[(size_t)n * K_CODES]);
#pragma unroll
    for (int j = 0; j < 16; j++) {
        int u = j * 128 + tid;               // uint4 index: 8 halves
        uint4 v = __ldcs(&rowp[u]);
        const uint32_t w[4] = {v.x, v.y, v.z, v.w};
#pragma unroll
        for (int q = 0; q < 4; q++) {
            __half2 p = *reinterpret_cast<const __half2*>(&w[q]);
            float lo = __low2float(p);
            float hi = __high2float(p);
            if (lo <= thr) {
                int pos = atomicAdd(&s_cnt, 1);
                if (pos < 256) s_list[pos] = u * 8 + q * 2;
            }
            if (hi <= thr) {
                int pos = atomicAdd(&s_cnt, 1);
                if (pos < 256) s_list[pos] = u * 8 + q * 2 + 1;
            }
        }
    }
    __syncthreads();

    int cnt = s_cnt < 256 ? s_cnt : 256;
    float sz = g_sz[n];
    for (int c = tid; c < cnt; c += 128) {
        int k = s_list[c];
        const float* er = emb + (size_t)k * D_DIM;
        float acc = 0.f;
#pragma unroll 8
        for (int d = 0; d < D_DIM; d++)
            acc = fmaf(s_z[d], er[d], acc);
        float dval = __fsub_rn(sz, __fmul_rn(2.0f, acc));
        unsigned long long key =
            ((unsigned long long)__float_as_uint(dval) << 32) | (unsigned int)k;
        atomicMin(&s_best, key);
    }
    __syncthreads();
    if (tid == 0) g_best[n] = s_best;
}

// ---------------------------------------------------------------------------
// finalize: 256 blocks = (32 n-groups) x (8 d-chunks); verified R1 math.
// ---------------------------------------------------------------------------
__global__ void vq_finalize_kernel(const float* __restrict__ z,
                                   const float* __restrict__ emb,
                                   float* __restrict__ out, int out_size) {
    __shared__ double sred[256];
    int ng = blockIdx.x >> 3;
    int dc = blockIdx.x & 7;
    int n  = ng * 256 + threadIdx.x;
    int b  = n >> 10;
    int hw = n & 1023;

    int k = (int)(unsigned int)(g_best[n] & 0xFFFFFFFFu);

    const float* e  = emb + (size_t)k * D_DIM;
    const float* zp = z   + (size_t)b * 262144 + hw;
    float*       op = out + (size_t)b * 262144 + hw;

    double lsum = 0.0;
#pragma unroll 8
    for (int d = dc * 32; d < dc * 32 + 32; d++) {
        float zv   = zp[(size_t)d * 1024];
        float ev   = e[d];
        float diff = __fsub_rn(ev, zv);          // fl(z_q - z)
        float q    = __fadd_rn(zv, diff);        // fl(z + fl(z_q - z))
        op[(size_t)d * 1024] = q;
        lsum += (double)diff * (double)diff;
    }

    if (dc == 0) {
        int idx_pos = 2097152 + 1 + n;
        if (idx_pos < out_size) out[idx_pos] = (float)k;
    }

    sred[threadIdx.x] = lsum;
    __syncthreads();
    for (int s = 128; s > 0; s >>= 1) {
        if (threadIdx.x < s) sred[threadIdx.x] += sred[threadIdx.x + s];
        __syncthreads();
    }
    if (threadIdx.x == 0) g_loss_part[blockIdx.x] = sred[0];
}

__global__ void vq_loss_kernel(float* __restrict__ out, int out_size) {
    if (threadIdx.x == 0 && blockIdx.x == 0) {
        double s = 0.0;
        for (int i = 0; i < 256; i++) s += g_loss_part[i];
        double mean = s / 2097152.0;
        if (2097152 < out_size) out[2097152] = (float)(mean * 1.25);
    }
}

// ---------------------------------------------------------------------------
extern "C" void kernel_launch(void* const* d_in, const int* in_sizes, int n_in,
                              void* d_out, int out_size) {
    const float* z   = (const float*)d_in[0];   // [8,256,32,32]
    const float* emb = (const float*)d_in[1];   // [16384,256]
    float* out = (float*)d_out;

    vq_init_kernel<<<32, 256>>>();
    vq_pack_z_kernel<<<32, 256>>>(z);
    vq_pack_e_kernel<<<4096, 256>>>(emb);

    dim3 grid(N_VEC / 128, K_CODES / 128);     // 64 x 128 = 8192 blocks
    vq_mma_kernel<<<grid, 256>>>();

    vq_scan_rescore_kernel<<<N_VEC, 128>>>(emb);
    vq_finalize_kernel<<<256, 256>>>(z, emb, out, out_size);
    vq_loss_kernel<<<1, 32>>>(out, out_size);
}

// round 12
// speedup vs baseline: 1.7434x; 1.1239x over previous
#include <cuda_runtime.h>
#include <cuda_bf16.h>
#include <cuda_fp16.h>
#include <cstdint>

#define N_VEC    8192
#define K_CODES  16384
#define D_DIM    256
#define N_TILES  128                // 128-code tiles per row
#define MARGIN_D1 4e-4f             // hard bound: 2.8e-4 + enc + bucket

// ------------------------- device scratch (globals) -------------------------
__device__ __nv_bfloat16      g_abf[N_VEC * D_DIM];     // z rows, bf16(rn)
__device__ __nv_bfloat16      g_bbf[K_CODES * D_DIM];   // emb rows, bf16(rn)
__device__ float              g_zf [N_VEC * D_DIM];     // z rows, fp32 packed
__device__ float              g_sz [N_VEC];
__device__ unsigned int       g_rowmin[N_VEC];          // bits of min d1 (>0)
__device__ unsigned long long g_best[N_VEC];            // (bits(d)<<32)|k
__device__ __half             g_d1[(size_t)N_VEC * K_CODES]; // rd(d1-1), 256MB
__device__ __half             g_blkmin[(size_t)N_VEC * N_TILES]; // tile mins, 2MB
__device__ double             g_loss_part[256];

// ------------------------------ PTX helpers --------------------------------
__device__ __forceinline__ uint32_t smem_u32(const void* p) {
    uint32_t a;
    asm("{ .reg .u64 t; cvta.to.shared.u64 t, %1; cvt.u32.u64 %0, t; }"
        : "=r"(a) : "l"(p));
    return a;
}
__device__ __forceinline__ void ldm_x4(uint32_t* r, uint32_t addr) {
    asm volatile("ldmatrix.sync.aligned.m8n8.x4.shared.b16 {%0,%1,%2,%3}, [%4];"
                 : "=r"(r[0]), "=r"(r[1]), "=r"(r[2]), "=r"(r[3]) : "r"(addr));
}
__device__ __forceinline__ void mma_bf16(float* c, const uint32_t* a,
                                         uint32_t b0, uint32_t b1) {
    asm volatile(
        "mma.sync.aligned.m16n8k16.row.col.f32.bf16.bf16.f32 "
        "{%0,%1,%2,%3}, {%4,%5,%6,%7}, {%8,%9}, {%0,%1,%2,%3};"
        : "+f"(c[0]), "+f"(c[1]), "+f"(c[2]), "+f"(c[3])
        : "r"(a[0]), "r"(a[1]), "r"(a[2]), "r"(a[3]), "r"(b0), "r"(b1));
}

// ---------------------------------------------------------------------------
__global__ void vq_init_kernel() {
    int i = blockIdx.x * blockDim.x + threadIdx.x;
    if (i < N_VEC) g_rowmin[i] = 0x7F800000u;   // +inf
}

// ---------------------------------------------------------------------------
// pack z -> zf (fp32 row-major), abf (bf16), sz (sequential chain, identical
// order to the R1 kernel that verified rel_err 0.0)
// ---------------------------------------------------------------------------
__global__ void vq_pack_z_kernel(const float* __restrict__ z) {
    int n  = blockIdx.x * blockDim.x + threadIdx.x;
    int b  = n >> 10;
    int hw = n & 1023;
    const float* zp = z + (size_t)b * 262144 + hw;
    float s = 0.f;
#pragma unroll 8
    for (int d = 0; d < D_DIM; d++) {
        float v = zp[(size_t)d * 1024];
        g_zf [n * D_DIM + d] = v;
        g_abf[n * D_DIM + d] = __float2bfloat16_rn(v);
        s = fmaf(v, v, s);
    }
    g_sz[n] = s;
}

__global__ void vq_pack_e_kernel(const float* __restrict__ emb) {
    int i0 = blockIdx.x * 1024 + threadIdx.x;
#pragma unroll
    for (int j = 0; j < 4; j++) {
        int i = i0 + j * 256;
        g_bbf[i] = __float2bfloat16_rn(emb[i]);
    }
}

// ---------------------------------------------------------------------------
// SINGLE-PASS bf16 HMMA GEMM — R11 mainloop (128x128, 8 warps of 32x64,
// register-prefetch, 2 blk/SM).  Epilogue (numerics identical to R8/R11):
//   - full d1 tile as fp16 rd(d1 - 1), streamed out with stcs
//   - per-row TILE min -> g_blkmin (new: scan index) and -> g_rowmin
// ---------------------------------------------------------------------------
__global__ __launch_bounds__(256, 2)
void vq_mma_kernel() {
    __shared__ __align__(16) __nv_bfloat16 sA[128][40];
    __shared__ __align__(16) __nv_bfloat16 sB[128][40];
    __shared__ __align__(16) __half s_d1[128][136];
    __shared__ unsigned int s_tilemin[128];

    const int tid  = threadIdx.x;
    const int lane = tid & 31;
    const int wid  = tid >> 5;
    const int wm   = wid >> 1;               // 0..3
    const int wn   = wid & 1;                // 0..1
    const int n0   = blockIdx.x * 128;       // z-row base
    const int k0   = blockIdx.y * 128;       // code base

    float acc[2][8][4];
#pragma unroll
    for (int mi = 0; mi < 2; mi++)
#pragma unroll
        for (int ni = 0; ni < 8; ni++)
#pragma unroll
            for (int r = 0; r < 4; r++) acc[mi][ni][r] = 0.f;

    const int lrow = tid >> 2;        // 0..63 (owns rows lrow, lrow+64)
    const int lq   = (tid & 3) * 8;   // bf16 col of 16B chunk

    const __nv_bfloat16* ap0 = &g_abf[(size_t)(n0 + lrow) * D_DIM + lq];
    const __nv_bfloat16* ap1 = ap0 + (size_t)64 * D_DIM;
    const __nv_bfloat16* bp0 = &g_bbf[(size_t)(k0 + lrow) * D_DIM + lq];
    const __nv_bfloat16* bp1 = bp0 + (size_t)64 * D_DIM;

    // prefetch chunk 0
    uint4 pa0 = *reinterpret_cast<const uint4*>(ap0);
    uint4 pa1 = *reinterpret_cast<const uint4*>(ap1);
    uint4 pb0 = *reinterpret_cast<const uint4*>(bp0);
    uint4 pb1 = *reinterpret_cast<const uint4*>(bp1);

    for (int kc = 0; kc < 8; kc++) {
        __syncthreads();   // previous chunk's readers done
        *reinterpret_cast<uint4*>(&sA[lrow     ][lq]) = pa0;
        *reinterpret_cast<uint4*>(&sA[lrow + 64][lq]) = pa1;
        *reinterpret_cast<uint4*>(&sB[lrow     ][lq]) = pb0;
        *reinterpret_cast<uint4*>(&sB[lrow + 64][lq]) = pb1;
        __syncthreads();

        if (kc < 7) {      // prefetch next chunk; latency overlaps compute
            const int kb = (kc + 1) * 32;
            pa0 = *reinterpret_cast<const uint4*>(ap0 + kb);
            pa1 = *reinterpret_cast<const uint4*>(ap1 + kb);
            pb0 = *reinterpret_cast<const uint4*>(bp0 + kb);
            pb1 = *reinterpret_cast<const uint4*>(bp1 + kb);
        }

#pragma unroll
        for (int ks = 0; ks < 2; ks++) {
            uint32_t a[2][4];
#pragma unroll
            for (int mi = 0; mi < 2; mi++) {
                int r = wm * 32 + mi * 16 + (lane & 15);
                int c = ks * 16 + (lane >> 4) * 8;
                ldm_x4(a[mi], smem_u32(&sA[r][c]));
            }
            uint32_t b[4][4];
#pragma unroll
            for (int g = 0; g < 4; g++) {
                int r = wn * 64 + g * 16 + (lane & 15);
                int c = ks * 16 + (lane >> 4) * 8;
                ldm_x4(b[g], smem_u32(&sB[r][c]));
            }
#pragma unroll
            for (int mi = 0; mi < 2; mi++)
#pragma unroll
                for (int g = 0; g < 4; g++) {
                    mma_bf16(acc[mi][2 * g],     a[mi], b[g][0], b[g][2]);
                    mma_bf16(acc[mi][2 * g + 1], a[mi], b[g][1], b[g][3]);
                }
        }
    }

    // ---- epilogue: d1 tile -> smem (fp16 rd), per-row tile mins ----
    if (tid < 128) s_tilemin[tid] = 0x7F800000u;
    __syncthreads();

#pragma unroll
    for (int mi = 0; mi < 2; mi++)
#pragma unroll
        for (int ci = 0; ci < 2; ci++) {
            int rl = wm * 32 + mi * 16 + ci * 8 + (lane >> 2);
            float mn = 3.402823466e+38f;
#pragma unroll
            for (int ni = 0; ni < 8; ni++) {
                float d0 = __fmaf_rn(-2.0f, acc[mi][ni][2 * ci],     1.0f);
                float d1 = __fmaf_rn(-2.0f, acc[mi][ni][2 * ci + 1], 1.0f);
                int col = wn * 64 + ni * 8 + (lane & 3) * 2;
                __half2 h = __halves2half2(
                    __float2half_rd(__fsub_rn(d0, 1.0f)),
                    __float2half_rd(__fsub_rn(d1, 1.0f)));
                *reinterpret_cast<__half2*>(&s_d1[rl][col]) = h;
                mn = fminf(mn, fminf(d0, d1));
            }
            mn = fminf(mn, __shfl_xor_sync(0xFFFFFFFFu, mn, 1));
            mn = fminf(mn, __shfl_xor_sync(0xFFFFFFFFu, mn, 2));
            if ((lane & 3) == 0)
                atomicMin(&s_tilemin[rl], __float_as_uint(mn));
        }
    __syncthreads();

    // per-row: fold tile min into global rowmin + write the tile-min index
    if (tid < 128) {
        unsigned int tm = s_tilemin[tid];
        atomicMin(&g_rowmin[n0 + tid], tm);
        g_blkmin[(size_t)(n0 + tid) * N_TILES + blockIdx.y] =
            __float2half_rd(__fsub_rn(__uint_as_float(tm), 1.0f));
    }

    // coalesced streaming store of the 128x128 fp16 tile (evict-first in L2)
#pragma unroll
    for (int i = 0; i < 8; i++) {
        int idx = i * 256 + tid;             // 0..2047 (uint4 units)
        int row = idx >> 4;
        int col = (idx & 15) * 8;
        float4 v = *reinterpret_cast<float4*>(&s_d1[row][col]);
        __stcs(reinterpret_cast<float4*>(
            &g_d1[(size_t)(n0 + row) * K_CODES + k0 + col]), v);
    }
}

// ---------------------------------------------------------------------------
// Scan v2 + exact rescore: one 128-thread block per z-row.
//  - read 128 tile mins (256 B); only qualifying tiles' d1 rows are touched
//  - individual codes <= rowmin-1+margin exactly rescored with the verified
//    R1 sequential fp32 chain; block-min lexicographic key
// ---------------------------------------------------------------------------
__global__ __launch_bounds__(128)
void vq_scan_rescore_kernel(const float* __restrict__ emb) {
    __shared__ float s_z[D_DIM];
    __shared__ int   s_tlist[32];
    __shared__ int   s_tcnt;
    __shared__ int   s_list[512];
    __shared__ int   s_cnt;
    __shared__ unsigned long long s_best;

    const int n   = blockIdx.x;
    const int tid = threadIdx.x;

    if (tid == 0) { s_tcnt = 0; s_cnt = 0; s_best = 0xFFFFFFFFFFFFFFFFULL; }
    s_z[tid]       = g_zf[(size_t)n * D_DIM + tid];
    s_z[tid + 128] = g_zf[(size_t)n * D_DIM + tid + 128];
    const float thr = __uint_as_float(g_rowmin[n]) - 1.0f + MARGIN_D1;
    __syncthreads();

    // stage 1: tile filter (256 B)
    {
        float bm = __half2float(g_blkmin[(size_t)n * N_TILES + tid]);
        if (bm <= thr) {
            int p = atomicAdd(&s_tcnt, 1);
            if (p < 32) s_tlist[p] = tid;
        }
    }
    __syncthreads();

    // stage 2: per-code filter within qualifying tiles (256 B each)
    int tc = s_tcnt < 32 ? s_tcnt : 32;
    for (int t = 0; t < tc; t++) {
        int kb = s_tlist[t] * 128;
        float v = __half2float(g_d1[(size_t)n * K_CODES + kb + tid]);
        if (v <= thr) {
            int p = atomicAdd(&s_cnt, 1);
            if (p < 512) s_list[p] = kb + tid;
        }
    }
    __syncthreads();

    // stage 3: exact rescore (verified R1 arithmetic)
    int cnt = s_cnt < 512 ? s_cnt : 512;
    float sz = g_sz[n];
    for (int c = tid; c < cnt; c += 128) {
        int k = s_list[c];
        const float* er = emb + (size_t)k * D_DIM;
        float acc = 0.f;
#pragma unroll 8
        for (int d = 0; d < D_DIM; d++)
            acc = fmaf(s_z[d], er[d], acc);
        float dval = __fsub_rn(sz, __fmul_rn(2.0f, acc));
        unsigned long long key =
            ((unsigned long long)__float_as_uint(dval) << 32) | (unsigned int)k;
        atomicMin(&s_best, key);
    }
    __syncthreads();
    if (tid == 0) g_best[n] = s_best;
}

// ---------------------------------------------------------------------------
// finalize: 256 blocks = (32 n-groups) x (8 d-chunks); verified R1 math.
// ---------------------------------------------------------------------------
__global__ void vq_finalize_kernel(const float* __restrict__ z,
                                   const float* __restrict__ emb,
                                   float* __restrict__ out, int out_size) {
    __shared__ double sred[256];
    int ng = blockIdx.x >> 3;
    int dc = blockIdx.x & 7;
    int n  = ng * 256 + threadIdx.x;
    int b  = n >> 10;
    int hw = n & 1023;

    int k = (int)(unsigned int)(g_best[n] & 0xFFFFFFFFu);

    const float* e  = emb + (size_t)k * D_DIM;
    const float* zp = z   + (size_t)b * 262144 + hw;
    float*       op = out + (size_t)b * 262144 + hw;

    double lsum = 0.0;
#pragma unroll 8
    for (int d = dc * 32; d < dc * 32 + 32; d++) {
        float zv   = zp[(size_t)d * 1024];
        float ev   = e[d];
        float diff = __fsub_rn(ev, zv);          // fl(z_q - z)
        float q    = __fadd_rn(zv, diff);        // fl(z + fl(z_q - z))
        op[(size_t)d * 1024] = q;
        lsum += (double)diff * (double)diff;
    }

    if (dc == 0) {
        int idx_pos = 2097152 + 1 + n;
        if (idx_pos < out_size) out[idx_pos] = (float)k;
    }

    sred[threadIdx.x] = lsum;
    __syncthreads();
    for (int s = 128; s > 0; s >>= 1) {
        if (threadIdx.x < s) sred[threadIdx.x] += sred[threadIdx.x + s];
        __syncthreads();
    }
    if (threadIdx.x == 0) g_loss_part[blockIdx.x] = sred[0];
}

__global__ void vq_loss_kernel(float* __restrict__ out, int out_size) {
    if (threadIdx.x == 0 && blockIdx.x == 0) {
        double s = 0.0;
        for (int i = 0; i < 256; i++) s += g_loss_part[i];
        double mean = s / 2097152.0;
        if (2097152 < out_size) out[2097152] = (float)(mean * 1.25);
    }
}

// ---------------------------------------------------------------------------
extern "C" void kernel_launch(void* const* d_in, const int* in_sizes, int n_in,
                              void* d_out, int out_size) {
    const float* z   = (const float*)d_in[0];   // [8,256,32,32]
    const float* emb = (const float*)d_in[1];   // [16384,256]
    float* out = (float*)d_out;

    vq_init_kernel<<<32, 256>>>();
    vq_pack_z_kernel<<<32, 256>>>(z);
    vq_pack_e_kernel<<<4096, 256>>>(emb);

    dim3 grid(N_VEC / 128, K_CODES / 128);     // 64 x 128 = 8192 blocks
    vq_mma_kernel<<<grid, 256>>>();

    vq_scan_rescore_kernel<<<N_VEC, 128>>>(emb);
    vq_finalize_kernel<<<256, 256>>>(z, emb, out, out_size);
    vq_loss_kernel<<<1, 32>>>(out, out_size);
}

// round 13
// speedup vs baseline: 2.1096x; 1.2100x over previous
#include <cuda_runtime.h>
#include <cuda_bf16.h>
#include <cuda_fp16.h>
#include <cstdint>

#define N_VEC    8192
#define K_CODES  16384
#define D_DIM    256
#define N_TILES  128                // 128-code tiles per row
#define MARGIN_D1 4e-4f             // hard bound: 2.8e-4 + enc + bucket

// ------------------------- device scratch (globals) -------------------------
__device__ __nv_bfloat16      g_abf[N_VEC * D_DIM];     // z rows, bf16(rn)
__device__ __nv_bfloat16      g_bbf[K_CODES * D_DIM];   // emb rows, bf16(rn)
__device__ float              g_zf [N_VEC * D_DIM];     // z rows, fp32 packed
__device__ float              g_sz [N_VEC];
__device__ unsigned int       g_rowmin[N_VEC];          // bits of min d1 (>0)
__device__ unsigned long long g_best[N_VEC];            // (bits(d)<<32)|k
__device__ __half             g_d1[(size_t)N_VEC * K_CODES]; // rd(d1-1), 256MB
__device__ __half             g_blkmin[(size_t)N_VEC * N_TILES]; // tile mins, 2MB
__device__ double             g_loss_part[256];

// ------------------------------ PTX helpers --------------------------------
__device__ __forceinline__ uint32_t smem_u32(const void* p) {
    uint32_t a;
    asm("{ .reg .u64 t; cvta.to.shared.u64 t, %1; cvt.u32.u64 %0, t; }"
        : "=r"(a) : "l"(p));
    return a;
}
__device__ __forceinline__ void ldm_x4(uint32_t* r, uint32_t addr) {
    asm volatile("ldmatrix.sync.aligned.m8n8.x4.shared.b16 {%0,%1,%2,%3}, [%4];"
                 : "=r"(r[0]), "=r"(r[1]), "=r"(r[2]), "=r"(r[3]) : "r"(addr));
}
__device__ __forceinline__ void mma_bf16(float* c, const uint32_t* a,
                                         uint32_t b0, uint32_t b1) {
    asm volatile(
        "mma.sync.aligned.m16n8k16.row.col.f32.bf16.bf16.f32 "
        "{%0,%1,%2,%3}, {%4,%5,%6,%7}, {%8,%9}, {%0,%1,%2,%3};"
        : "+f"(c[0]), "+f"(c[1]), "+f"(c[2]), "+f"(c[3])
        : "r"(a[0]), "r"(a[1]), "r"(a[2]), "r"(a[3]), "r"(b0), "r"(b1));
}

// ---------------------------------------------------------------------------
// pack z -> zf (fp32 row-major), abf (bf16), sz (sequential chain, identical
// order to the R1 kernel that verified rel_err 0.0).  128 blocks x 64 threads
// spreads the chains across SMs (mapping n = blk*64+tid keeps hw coalesced).
// ---------------------------------------------------------------------------
__global__ void vq_pack_z_kernel(const float* __restrict__ z) {
    int n  = blockIdx.x * 64 + threadIdx.x;
    int b  = n >> 10;
    int hw = n & 1023;
    const float* zp = z + (size_t)b * 262144 + hw;
    float s = 0.f;
#pragma unroll 8
    for (int d = 0; d < D_DIM; d++) {
        float v = zp[(size_t)d * 1024];
        g_zf [n * D_DIM + d] = v;
        g_abf[n * D_DIM + d] = __float2bfloat16_rn(v);
        s = fmaf(v, v, s);
    }
    g_sz[n] = s;
}

// pack emb -> bf16; also folds the g_rowmin init (one fewer launch)
__global__ void vq_pack_e_kernel(const float* __restrict__ emb) {
    int gid = blockIdx.x * 256 + threadIdx.x;
    if (gid < N_VEC) g_rowmin[gid] = 0x7F800000u;   // +inf
    int i0 = blockIdx.x * 1024 + threadIdx.x;
#pragma unroll
    for (int j = 0; j < 4; j++) {
        int i = i0 + j * 256;
        g_bbf[i] = __float2bfloat16_rn(emb[i]);
    }
}

// ---------------------------------------------------------------------------
// SINGLE-PASS bf16 HMMA GEMM — 128x128 tile, 8 warps of 32x64, 2 blk/SM,
// register-prefetch + DOUBLE-BUFFERED smem (one barrier per chunk).
// Epilogue (numerics identical to verified R12):
//   - full d1 tile as fp16 rd(d1 - 1), streamed out with stcs
//   - per-row tile min -> g_blkmin (scan index) and -> g_rowmin
// ---------------------------------------------------------------------------
__global__ __launch_bounds__(256, 2)
void vq_mma_kernel() {
    // [0,20480): A buf0|buf1   [20480,40960): B buf0|buf1
    // epilogue d1 tile (34816 B) overlays the (dead) buffers
    __shared__ __align__(16) char s_raw[40960];
    __shared__ unsigned int s_tilemin[128];

    __nv_bfloat16 (*sA)[40] = reinterpret_cast<__nv_bfloat16(*)[40]>(s_raw);
    __nv_bfloat16 (*sB)[40] =
        reinterpret_cast<__nv_bfloat16(*)[40]>(s_raw + 20480);
    __half (*s_d1)[136] = reinterpret_cast<__half(*)[136]>(s_raw);

    const int tid  = threadIdx.x;
    const int lane = tid & 31;
    const int wid  = tid >> 5;
    const int wm   = wid >> 1;               // 0..3
    const int wn   = wid & 1;                // 0..1
    const int n0   = blockIdx.x * 128;       // z-row base
    const int k0   = blockIdx.y * 128;       // code base

    float acc[2][8][4];
#pragma unroll
    for (int mi = 0; mi < 2; mi++)
#pragma unroll
        for (int ni = 0; ni < 8; ni++)
#pragma unroll
            for (int r = 0; r < 4; r++) acc[mi][ni][r] = 0.f;

    if (tid < 128) s_tilemin[tid] = 0x7F800000u;

    const int lrow = tid >> 2;        // 0..63 (owns rows lrow, lrow+64)
    const int lq   = (tid & 3) * 8;   // bf16 col of 16B chunk

    const __nv_bfloat16* ap0 = &g_abf[(size_t)(n0 + lrow) * D_DIM + lq];
    const __nv_bfloat16* ap1 = ap0 + (size_t)64 * D_DIM;
    const __nv_bfloat16* bp0 = &g_bbf[(size_t)(k0 + lrow) * D_DIM + lq];
    const __nv_bfloat16* bp1 = bp0 + (size_t)64 * D_DIM;

    // prologue: chunk 0 -> buffer 0
    {
        uint4 a0 = *reinterpret_cast<const uint4*>(ap0);
        uint4 a1 = *reinterpret_cast<const uint4*>(ap1);
        uint4 b0 = *reinterpret_cast<const uint4*>(bp0);
        uint4 b1 = *reinterpret_cast<const uint4*>(bp1);
        *reinterpret_cast<uint4*>(&sA[lrow     ][lq]) = a0;
        *reinterpret_cast<uint4*>(&sA[lrow + 64][lq]) = a1;
        *reinterpret_cast<uint4*>(&sB[lrow     ][lq]) = b0;
        *reinterpret_cast<uint4*>(&sB[lrow + 64][lq]) = b1;
    }
    __syncthreads();

#pragma unroll
    for (int kc = 0; kc < 8; kc++) {
        const int cbuf = (kc & 1) * 128;          // compute buffer
        const int nbuf = ((kc + 1) & 1) * 128;    // fill buffer

        uint4 pa0, pa1, pb0, pb1;
        if (kc < 7) {      // LDG next chunk; latency overlaps the MMAs below
            const int kb = (kc + 1) * 32;
            pa0 = *reinterpret_cast<const uint4*>(ap0 + kb);
            pa1 = *reinterpret_cast<const uint4*>(ap1 + kb);
            pb0 = *reinterpret_cast<const uint4*>(bp0 + kb);
            pb1 = *reinterpret_cast<const uint4*>(bp1 + kb);
        }

#pragma unroll
        for (int ks = 0; ks < 2; ks++) {
            uint32_t a[2][4];
#pragma unroll
            for (int mi = 0; mi < 2; mi++) {
                int r = wm * 32 + mi * 16 + (lane & 15);
                int c = ks * 16 + (lane >> 4) * 8;
                ldm_x4(a[mi], smem_u32(&sA[cbuf + r][c]));
            }
            uint32_t b[4][4];
#pragma unroll
            for (int g = 0; g < 4; g++) {
                int r = wn * 64 + g * 16 + (lane & 15);
                int c = ks * 16 + (lane >> 4) * 8;
                ldm_x4(b[g], smem_u32(&sB[cbuf + r][c]));
            }
#pragma unroll
            for (int mi = 0; mi < 2; mi++)
#pragma unroll
                for (int g = 0; g < 4; g++) {
                    mma_bf16(acc[mi][2 * g],     a[mi], b[g][0], b[g][2]);
                    mma_bf16(acc[mi][2 * g + 1], a[mi], b[g][1], b[g][3]);
                }
        }

        if (kc < 7) {      // fill other buffer (readers drained at last barrier)
            *reinterpret_cast<uint4*>(&sA[nbuf + lrow     ][lq]) = pa0;
            *reinterpret_cast<uint4*>(&sA[nbuf + lrow + 64][lq]) = pa1;
            *reinterpret_cast<uint4*>(&sB[nbuf + lrow     ][lq]) = pb0;
            *reinterpret_cast<uint4*>(&sB[nbuf + lrow + 64][lq]) = pb1;
        }
        __syncthreads();   // single barrier per chunk
    }

    // ---- epilogue: d1 tile -> smem (fp16 rd), per-row tile mins ----
    // (all buffer readers drained at the final loop barrier; s_d1 overlays)
#pragma unroll
    for (int mi = 0; mi < 2; mi++)
#pragma unroll
        for (int ci = 0; ci < 2; ci++) {
            int rl = wm * 32 + mi * 16 + ci * 8 + (lane >> 2);
            float mn = 3.402823466e+38f;
#pragma unroll
            for (int ni = 0; ni < 8; ni++) {
                float d0 = __fmaf_rn(-2.0f, acc[mi][ni][2 * ci],     1.0f);
                float d1 = __fmaf_rn(-2.0f, acc[mi][ni][2 * ci + 1], 1.0f);
                int col = wn * 64 + ni * 8 + (lane & 3) * 2;
                __half2 h = __halves2half2(
                    __float2half_rd(__fsub_rn(d0, 1.0f)),
                    __float2half_rd(__fsub_rn(d1, 1.0f)));
                *reinterpret_cast<__half2*>(&s_d1[rl][col]) = h;
                mn = fminf(mn, fminf(d0, d1));
            }
            mn = fminf(mn, __shfl_xor_sync(0xFFFFFFFFu, mn, 1));
            mn = fminf(mn, __shfl_xor_sync(0xFFFFFFFFu, mn, 2));
            if ((lane & 3) == 0)
                atomicMin(&s_tilemin[rl], __float_as_uint(mn));
        }
    __syncthreads();

    // per-row: fold tile min into global rowmin + write the tile-min index
    if (tid < 128) {
        unsigned int tm = s_tilemin[tid];
        atomicMin(&g_rowmin[n0 + tid], tm);
        g_blkmin[(size_t)(n0 + tid) * N_TILES + blockIdx.y] =
            __float2half_rd(__fsub_rn(__uint_as_float(tm), 1.0f));
    }

    // coalesced streaming store of the 128x128 fp16 tile (evict-first in L2)
#pragma unroll
    for (int i = 0; i < 8; i++) {
        int idx = i * 256 + tid;             // 0..2047 (uint4 units)
        int row = idx >> 4;
        int col = (idx & 15) * 8;
        float4 v = *reinterpret_cast<float4*>(&s_d1[row][col]);
        __stcs(reinterpret_cast<float4*>(
            &g_d1[(size_t)(n0 + row) * K_CODES + k0 + col]), v);
    }
}

// ---------------------------------------------------------------------------
// Scan + exact rescore: one 128-thread block per z-row (verified R12).
// ---------------------------------------------------------------------------
__global__ __launch_bounds__(128)
void vq_scan_rescore_kernel(const float* __restrict__ emb) {
    __shared__ float s_z[D_DIM];
    __shared__ int   s_tlist[32];
    __shared__ int   s_tcnt;
    __shared__ int   s_list[512];
    __shared__ int   s_cnt;
    __shared__ unsigned long long s_best;

    const int n   = blockIdx.x;
    const int tid = threadIdx.x;

    if (tid == 0) { s_tcnt = 0; s_cnt = 0; s_best = 0xFFFFFFFFFFFFFFFFULL; }
    s_z[tid]       = g_zf[(size_t)n * D_DIM + tid];
    s_z[tid + 128] = g_zf[(size_t)n * D_DIM + tid + 128];
    const float thr = __uint_as_float(g_rowmin[n]) - 1.0f + MARGIN_D1;
    __syncthreads();

    // stage 1: tile filter (256 B)
    {
        float bm = __half2float(g_blkmin[(size_t)n * N_TILES + tid]);
        if (bm <= thr) {
            int p = atomicAdd(&s_tcnt, 1);
            if (p < 32) s_tlist[p] = tid;
        }
    }
    __syncthreads();

    // stage 2: per-code filter within qualifying tiles (256 B each)
    int tc = s_tcnt < 32 ? s_tcnt : 32;
    for (int t = 0; t < tc; t++) {
        int kb = s_tlist[t] * 128;
        float v = __half2float(g_d1[(size_t)n * K_CODES + kb + tid]);
        if (v <= thr) {
            int p = atomicAdd(&s_cnt, 1);
            if (p < 512) s_list[p] = kb + tid;
        }
    }
    __syncthreads();

    // stage 3: exact rescore (verified R1 arithmetic)
    int cnt = s_cnt < 512 ? s_cnt : 512;
    float sz = g_sz[n];
    for (int c = tid; c < cnt; c += 128) {
        int k = s_list[c];
        const float* er = emb + (size_t)k * D_DIM;
        float acc = 0.f;
#pragma unroll 8
        for (int d = 0; d < D_DIM; d++)
            acc = fmaf(s_z[d], er[d], acc);
        float dval = __fsub_rn(sz, __fmul_rn(2.0f, acc));
        unsigned long long key =
            ((unsigned long long)__float_as_uint(dval) << 32) | (unsigned int)k;
        atomicMin(&s_best, key);
    }
    __syncthreads();
    if (tid == 0) g_best[n] = s_best;
}

// ---------------------------------------------------------------------------
// finalize: 256 blocks = (32 n-groups) x (8 d-chunks); verified R1 math.
// ---------------------------------------------------------------------------
__global__ void vq_finalize_kernel(const float* __restrict__ z,
                                   const float* __restrict__ emb,
                                   float* __restrict__ out, int out_size) {
    __shared__ double sred[256];
    int ng = blockIdx.x >> 3;
    int dc = blockIdx.x & 7;
    int n  = ng * 256 + threadIdx.x;
    int b  = n >> 10;
    int hw = n & 1023;

    int k = (int)(unsigned int)(g_best[n] & 0xFFFFFFFFu);

    const float* e  = emb + (size_t)k * D_DIM;
    const float* zp = z   + (size_t)b * 262144 + hw;
    float*       op = out + (size_t)b * 262144 + hw;

    double lsum = 0.0;
#pragma unroll 8
    for (int d = dc * 32; d < dc * 32 + 32; d++) {
        float zv   = zp[(size_t)d * 1024];
        float ev   = e[d];
        float diff = __fsub_rn(ev, zv);          // fl(z_q - z)
        float q    = __fadd_rn(zv, diff);        // fl(z + fl(z_q - z))
        op[(size_t)d * 1024] = q;
        lsum += (double)diff * (double)diff;
    }

    if (dc == 0) {
        int idx_pos = 2097152 + 1 + n;
        if (idx_pos < out_size) out[idx_pos] = (float)k;
    }

    sred[threadIdx.x] = lsum;
    __syncthreads();
    for (int s = 128; s > 0; s >>= 1) {
        if (threadIdx.x < s) sred[threadIdx.x] += sred[threadIdx.x + s];
        __syncthreads();
    }
    if (threadIdx.x == 0) g_loss_part[blockIdx.x] = sred[0];
}

__global__ void vq_loss_kernel(float* __restrict__ out, int out_size) {
    if (threadIdx.x == 0 && blockIdx.x == 0) {
        double s = 0.0;
        for (int i = 0; i < 256; i++) s += g_loss_part[i];
        double mean = s / 2097152.0;
        if (2097152 < out_size) out[2097152] = (float)(mean * 1.25);
    }
}

// ---------------------------------------------------------------------------
extern "C" void kernel_launch(void* const* d_in, const int* in_sizes, int n_in,
                              void* d_out, int out_size) {
    const float* z   = (const float*)d_in[0];   // [8,256,32,32]
    const float* emb = (const float*)d_in[1];   // [16384,256]
    float* out = (float*)d_out;

    vq_pack_z_kernel<<<128, 64>>>(z);
    vq_pack_e_kernel<<<4096, 256>>>(emb);       // also inits g_rowmin

    dim3 grid(N_VEC / 128, K_CODES / 128);     // 64 x 128 = 8192 blocks
    vq_mma_kernel<<<grid, 256>>>();

    vq_scan_rescore_kernel<<<N_VEC, 128>>>(emb);
    vq_finalize_kernel<<<256, 256>>>(z, emb, out, out_size);
    vq_loss_kernel<<<1, 32>>>(out, out_size);
}

// round 14
// speedup vs baseline: 2.2564x; 1.0696x over previous
#include <cuda_runtime.h>
#include <cuda_bf16.h>
#include <cuda_fp16.h>
#include <cstdint>

#define N_VEC    8192
#define K_CODES  16384
#define D_DIM    256
#define N_TILES  128                // 128-code tiles per row
#define MARGIN_D1 4e-4f             // hard bound: 2.8e-4 + enc + bucket

// ------------------------- device scratch (globals) -------------------------
__device__ __nv_bfloat16      g_abf[N_VEC * D_DIM];     // z rows, bf16(rn)
__device__ __nv_bfloat16      g_bbf[K_CODES * D_DIM];   // emb rows, bf16(rn)
__device__ float              g_zf [N_VEC * D_DIM];     // z rows, fp32 packed
__device__ float              g_sz [N_VEC];
__device__ unsigned int       g_rowmin[N_VEC];          // bits of min d1 (>0)
__device__ unsigned long long g_best[N_VEC];            // (bits(d)<<32)|k
__device__ __half             g_d1[(size_t)N_VEC * K_CODES]; // rd(d1-1), sparse
__device__ __half             g_blkmin[(size_t)N_VEC * N_TILES]; // tile mins
__device__ double             g_loss_part[256];

// ------------------------------ PTX helpers --------------------------------
__device__ __forceinline__ uint32_t smem_u32(const void* p) {
    uint32_t a;
    asm("{ .reg .u64 t; cvta.to.shared.u64 t, %1; cvt.u32.u64 %0, t; }"
        : "=r"(a) : "l"(p));
    return a;
}
__device__ __forceinline__ void ldm_x4(uint32_t* r, uint32_t addr) {
    asm volatile("ldmatrix.sync.aligned.m8n8.x4.shared.b16 {%0,%1,%2,%3}, [%4];"
                 : "=r"(r[0]), "=r"(r[1]), "=r"(r[2]), "=r"(r[3]) : "r"(addr));
}
__device__ __forceinline__ void mma_bf16(float* c, const uint32_t* a,
                                         uint32_t b0, uint32_t b1) {
    asm volatile(
        "mma.sync.aligned.m16n8k16.row.col.f32.bf16.bf16.f32 "
        "{%0,%1,%2,%3}, {%4,%5,%6,%7}, {%8,%9}, {%0,%1,%2,%3};"
        : "+f"(c[0]), "+f"(c[1]), "+f"(c[2]), "+f"(c[3])
        : "r"(a[0]), "r"(a[1]), "r"(a[2]), "r"(a[3]), "r"(b0), "r"(b1));
}

// ---------------------------------------------------------------------------
// pack z -> zf (fp32 row-major), abf (bf16), sz (sequential chain, identical
// order to the R1 kernel that verified rel_err 0.0)
// ---------------------------------------------------------------------------
__global__ void vq_pack_z_kernel(const float* __restrict__ z) {
    int n  = blockIdx.x * 64 + threadIdx.x;
    int b  = n >> 10;
    int hw = n & 1023;
    const float* zp = z + (size_t)b * 262144 + hw;
    float s = 0.f;
#pragma unroll 8
    for (int d = 0; d < D_DIM; d++) {
        float v = zp[(size_t)d * 1024];
        g_zf [n * D_DIM + d] = v;
        g_abf[n * D_DIM + d] = __float2bfloat16_rn(v);
        s = fmaf(v, v, s);
    }
    g_sz[n] = s;
}

// pack emb -> bf16; also folds the g_rowmin init (one fewer launch)
__global__ void vq_pack_e_kernel(const float* __restrict__ emb) {
    int gid = blockIdx.x * 256 + threadIdx.x;
    if (gid < N_VEC) g_rowmin[gid] = 0x7F800000u;   // +inf
    int i0 = blockIdx.x * 1024 + threadIdx.x;
#pragma unroll
    for (int j = 0; j < 4; j++) {
        int i = i0 + j * 256;
        g_bbf[i] = __float2bfloat16_rn(emb[i]);
    }
}

// ---------------------------------------------------------------------------
// SINGLE-PASS bf16 HMMA GEMM — R13 mainloop (verified): 128x128 tile, 8 warps
// of 32x64, 2 blk/SM, register-prefetch + double-buffered smem, 1 barrier.
// Epilogue: d1 tile -> smem (fp16 rd, identical numerics), then the global
// stcs of each ROW is SKIPPED when that row's tile-min provably cannot
// qualify against the (monotonically decreasing) running rowmin + margin —
// every finally-qualifying tile is still written.
// ---------------------------------------------------------------------------
__global__ __launch_bounds__(256, 2)
void vq_mma_kernel() {
    __shared__ __align__(16) char s_raw[40960];
    __shared__ unsigned int s_tilemin[128];   // then reused as write-flag

    __nv_bfloat16 (*sA)[40] = reinterpret_cast<__nv_bfloat16(*)[40]>(s_raw);
    __nv_bfloat16 (*sB)[40] =
        reinterpret_cast<__nv_bfloat16(*)[40]>(s_raw + 20480);
    __half (*s_d1)[136] = reinterpret_cast<__half(*)[136]>(s_raw);

    const int tid  = threadIdx.x;
    const int lane = tid & 31;
    const int wid  = tid >> 5;
    const int wm   = wid >> 1;               // 0..3
    const int wn   = wid & 1;                // 0..1
    const int n0   = blockIdx.x * 128;       // z-row base
    const int k0   = blockIdx.y * 128;       // code base

    float acc[2][8][4];
#pragma unroll
    for (int mi = 0; mi < 2; mi++)
#pragma unroll
        for (int ni = 0; ni < 8; ni++)
#pragma unroll
            for (int r = 0; r < 4; r++) acc[mi][ni][r] = 0.f;

    if (tid < 128) s_tilemin[tid] = 0x7F800000u;

    const int lrow = tid >> 2;
    const int lq   = (tid & 3) * 8;

    const __nv_bfloat16* ap0 = &g_abf[(size_t)(n0 + lrow) * D_DIM + lq];
    const __nv_bfloat16* ap1 = ap0 + (size_t)64 * D_DIM;
    const __nv_bfloat16* bp0 = &g_bbf[(size_t)(k0 + lrow) * D_DIM + lq];
    const __nv_bfloat16* bp1 = bp0 + (size_t)64 * D_DIM;

    // prologue: chunk 0 -> buffer 0
    {
        uint4 a0 = *reinterpret_cast<const uint4*>(ap0);
        uint4 a1 = *reinterpret_cast<const uint4*>(ap1);
        uint4 b0 = *reinterpret_cast<const uint4*>(bp0);
        uint4 b1 = *reinterpret_cast<const uint4*>(bp1);
        *reinterpret_cast<uint4*>(&sA[lrow     ][lq]) = a0;
        *reinterpret_cast<uint4*>(&sA[lrow + 64][lq]) = a1;
        *reinterpret_cast<uint4*>(&sB[lrow     ][lq]) = b0;
        *reinterpret_cast<uint4*>(&sB[lrow + 64][lq]) = b1;
    }
    __syncthreads();

#pragma unroll
    for (int kc = 0; kc < 8; kc++) {
        const int cbuf = (kc & 1) * 128;
        const int nbuf = ((kc + 1) & 1) * 128;

        uint4 pa0, pa1, pb0, pb1;
        if (kc < 7) {
            const int kb = (kc + 1) * 32;
            pa0 = *reinterpret_cast<const uint4*>(ap0 + kb);
            pa1 = *reinterpret_cast<const uint4*>(ap1 + kb);
            pb0 = *reinterpret_cast<const uint4*>(bp0 + kb);
            pb1 = *reinterpret_cast<const uint4*>(bp1 + kb);
        }

#pragma unroll
        for (int ks = 0; ks < 2; ks++) {
            uint32_t a[2][4];
#pragma unroll
            for (int mi = 0; mi < 2; mi++) {
                int r = wm * 32 + mi * 16 + (lane & 15);
                int c = ks * 16 + (lane >> 4) * 8;
                ldm_x4(a[mi], smem_u32(&sA[cbuf + r][c]));
            }
            uint32_t b[4][4];
#pragma unroll
            for (int g = 0; g < 4; g++) {
                int r = wn * 64 + g * 16 + (lane & 15);
                int c = ks * 16 + (lane >> 4) * 8;
                ldm_x4(b[g], smem_u32(&sB[cbuf + r][c]));
            }
#pragma unroll
            for (int mi = 0; mi < 2; mi++)
#pragma unroll
                for (int g = 0; g < 4; g++) {
                    mma_bf16(acc[mi][2 * g],     a[mi], b[g][0], b[g][2]);
                    mma_bf16(acc[mi][2 * g + 1], a[mi], b[g][1], b[g][3]);
                }
        }

        if (kc < 7) {
            *reinterpret_cast<uint4*>(&sA[nbuf + lrow     ][lq]) = pa0;
            *reinterpret_cast<uint4*>(&sA[nbuf + lrow + 64][lq]) = pa1;
            *reinterpret_cast<uint4*>(&sB[nbuf + lrow     ][lq]) = pb0;
            *reinterpret_cast<uint4*>(&sB[nbuf + lrow + 64][lq]) = pb1;
        }
        __syncthreads();
    }

    // ---- epilogue: d1 tile -> smem (fp16 rd), per-row tile mins ----
#pragma unroll
    for (int mi = 0; mi < 2; mi++)
#pragma unroll
        for (int ci = 0; ci < 2; ci++) {
            int rl = wm * 32 + mi * 16 + ci * 8 + (lane >> 2);
            float mn = 3.402823466e+38f;
#pragma unroll
            for (int ni = 0; ni < 8; ni++) {
                float d0 = __fmaf_rn(-2.0f, acc[mi][ni][2 * ci],     1.0f);
                float d1 = __fmaf_rn(-2.0f, acc[mi][ni][2 * ci + 1], 1.0f);
                int col = wn * 64 + ni * 8 + (lane & 3) * 2;
                __half2 h = __halves2half2(
                    __float2half_rd(__fsub_rn(d0, 1.0f)),
                    __float2half_rd(__fsub_rn(d1, 1.0f)));
                *reinterpret_cast<__half2*>(&s_d1[rl][col]) = h;
                mn = fminf(mn, fminf(d0, d1));
            }
            mn = fminf(mn, __shfl_xor_sync(0xFFFFFFFFu, mn, 1));
            mn = fminf(mn, __shfl_xor_sync(0xFFFFFFFFu, mn, 2));
            if ((lane & 3) == 0)
                atomicMin(&s_tilemin[rl], __float_as_uint(mn));
        }
    __syncthreads();

    // per-row: rowmin exchange, tile-min index write, survivability flag
    unsigned int flag = 0;
    if (tid < 128) {
        unsigned int tm  = s_tilemin[tid];
        unsigned int old = atomicMin(&g_rowmin[n0 + tid], tm);
        unsigned int run = old < tm ? old : tm;     // running >= final rowmin
        __half hv = __float2half_rd(
            __fsub_rn(__uint_as_float(tm), 1.0f));
        g_blkmin[(size_t)(n0 + tid) * N_TILES + blockIdx.y] = hv;
        // same compare form as the scan: qualifies only if
        // rd(tm-1) <= final-1+margin <= run-1+margin
        flag = (__half2float(hv) <=
                __uint_as_float(run) - 1.0f + MARGIN_D1) ? 1u : 0u;
    }
    __syncthreads();
    if (tid < 128) s_tilemin[tid] = flag;   // reuse as per-row write flag
    __syncthreads();

    // streaming store of the fp16 tile — ONLY rows that can still qualify
#pragma unroll
    for (int i = 0; i < 8; i++) {
        int idx = i * 256 + tid;             // 0..2047 (uint4 units)
        int row = idx >> 4;
        int col = (idx & 15) * 8;
        if (s_tilemin[row]) {
            float4 v = *reinterpret_cast<float4*>(&s_d1[row][col]);
            __stcs(reinterpret_cast<float4*>(
                &g_d1[(size_t)(n0 + row) * K_CODES + k0 + col]), v);
        }
    }
}

// ---------------------------------------------------------------------------
// Scan + exact rescore: one 128-thread block per z-row (verified R12/R13).
// ---------------------------------------------------------------------------
__global__ __launch_bounds__(128)
void vq_scan_rescore_kernel(const float* __restrict__ emb) {
    __shared__ float s_z[D_DIM];
    __shared__ int   s_tlist[32];
    __shared__ int   s_tcnt;
    __shared__ int   s_list[512];
    __shared__ int   s_cnt;
    __shared__ unsigned long long s_best;

    const int n   = blockIdx.x;
    const int tid = threadIdx.x;

    if (tid == 0) { s_tcnt = 0; s_cnt = 0; s_best = 0xFFFFFFFFFFFFFFFFULL; }
    s_z[tid]       = g_zf[(size_t)n * D_DIM + tid];
    s_z[tid + 128] = g_zf[(size_t)n * D_DIM + tid + 128];
    const float thr = __uint_as_float(g_rowmin[n]) - 1.0f + MARGIN_D1;
    __syncthreads();

    // stage 1: tile filter (256 B)
    {
        float bm = __half2float(g_blkmin[(size_t)n * N_TILES + tid]);
        if (bm <= thr) {
            int p = atomicAdd(&s_tcnt, 1);
            if (p < 32) s_tlist[p] = tid;
        }
    }
    __syncthreads();

    // stage 2: per-code filter within qualifying tiles (uint2 = 4 halves)
    int tc = s_tcnt < 32 ? s_tcnt : 32;
    for (int t = 0; t < tc; t++) {
        int kb = s_tlist[t] * 128;
        if (tid < 32) {
            uint2 v = __ldcs(reinterpret_cast<const uint2*>(
                &g_d1[(size_t)n * K_CODES + kb + tid * 4]));
            __half2 p0 = *reinterpret_cast<__half2*>(&v.x);
            __half2 p1 = *reinterpret_cast<__half2*>(&v.y);
            float m0 = __low2float(p0), m1 = __high2float(p0);
            float m2 = __low2float(p1), m3 = __high2float(p1);
            int kbase = kb + tid * 4;
            if (m0 <= thr) { int p = atomicAdd(&s_cnt, 1); if (p < 512) s_list[p] = kbase + 0; }
            if (m1 <= thr) { int p = atomicAdd(&s_cnt, 1); if (p < 512) s_list[p] = kbase + 1; }
            if (m2 <= thr) { int p = atomicAdd(&s_cnt, 1); if (p < 512) s_list[p] = kbase + 2; }
            if (m3 <= thr) { int p = atomicAdd(&s_cnt, 1); if (p < 512) s_list[p] = kbase + 3; }
        }
    }
    __syncthreads();

    // stage 3: exact rescore (verified R1 arithmetic)
    int cnt = s_cnt < 512 ? s_cnt : 512;
    float sz = g_sz[n];
    for (int c = tid; c < cnt; c += 128) {
        int k = s_list[c];
        const float* er = emb + (size_t)k * D_DIM;
        float acc = 0.f;
#pragma unroll 8
        for (int d = 0; d < D_DIM; d++)
            acc = fmaf(s_z[d], er[d], acc);
        float dval = __fsub_rn(sz, __fmul_rn(2.0f, acc));
        unsigned long long key =
            ((unsigned long long)__float_as_uint(dval) << 32) | (unsigned int)k;
        atomicMin(&s_best, key);
    }
    __syncthreads();
    if (tid == 0) g_best[n] = s_best;
}

// ---------------------------------------------------------------------------
// finalize: 256 blocks = (32 n-groups) x (8 d-chunks); verified R1 math.
// ---------------------------------------------------------------------------
__global__ void vq_finalize_kernel(const float* __restrict__ z,
                                   const float* __restrict__ emb,
                                   float* __restrict__ out, int out_size) {
    __shared__ double sred[256];
    int ng = blockIdx.x >> 3;
    int dc = blockIdx.x & 7;
    int n  = ng * 256 + threadIdx.x;
    int b  = n >> 10;
    int hw = n & 1023;

    int k = (int)(unsigned int)(g_best[n] & 0xFFFFFFFFu);

    const float* e  = emb + (size_t)k * D_DIM;
    const float* zp = z   + (size_t)b * 262144 + hw;
    float*       op = out + (size_t)b * 262144 + hw;

    double lsum = 0.0;
#pragma unroll 8
    for (int d = dc * 32; d < dc * 32 + 32; d++) {
        float zv   = zp[(size_t)d * 1024];
        float ev   = e[d];
        float diff = __fsub_rn(ev, zv);          // fl(z_q - z)
        float q    = __fadd_rn(zv, diff);        // fl(z + fl(z_q - z))
        op[(size_t)d * 1024] = q;
        lsum += (double)diff * (double)diff;
    }

    if (dc == 0) {
        int idx_pos = 2097152 + 1 + n;
        if (idx_pos < out_size) out[idx_pos] = (float)k;
    }

    sred[threadIdx.x] = lsum;
    __syncthreads();
    for (int s = 128; s > 0; s >>= 1) {
        if (threadIdx.x < s) sred[threadIdx.x] += sred[threadIdx.x + s];
        __syncthreads();
    }
    if (threadIdx.x == 0) g_loss_part[blockIdx.x] = sred[0];
}

__global__ void vq_loss_kernel(float* __restrict__ out, int out_size) {
    if (threadIdx.x == 0 && blockIdx.x == 0) {
        double s = 0.0;
        for (int i = 0; i < 256; i++) s += g_loss_part[i];
        double mean = s / 2097152.0;
        if (2097152 < out_size) out[2097152] = (float)(mean * 1.25);
    }
}

// ---------------------------------------------------------------------------
extern "C" void kernel_launch(void* const* d_in, const int* in_sizes, int n_in,
                              void* d_out, int out_size) {
    const float* z   = (const float*)d_in[0];   // [8,256,32,32]
    const float* emb = (const float*)d_in[1];   // [16384,256]
    float* out = (float*)d_out;

    vq_pack_z_kernel<<<128, 64>>>(z);
    vq_pack_e_kernel<<<4096, 256>>>(emb);       // also inits g_rowmin

    dim3 grid(N_VEC / 128, K_CODES / 128);     // 64 x 128 = 8192 blocks
    vq_mma_kernel<<<grid, 256>>>();

    vq_scan_rescore_kernel<<<N_VEC, 128>>>(emb);
    vq_finalize_kernel<<<256, 256>>>(z, emb, out, out_size);
    vq_loss_kernel<<<1, 32>>>(out, out_size);
}

// round 15
// speedup vs baseline: 2.3562x; 1.0442x over previous
#include <cuda_runtime.h>
#include <cuda_bf16.h>
#include <cuda_fp16.h>
#include <cstdint>

#define N_VEC    8192
#define K_CODES  16384
#define D_DIM    256
#define N_TILES  128                // 128-code tiles per row
#define MARGIN_D1 4e-4f             // hard bound: 2.8e-4 + enc + bucket

// ------------------------- device scratch (globals) -------------------------
__device__ __nv_bfloat16      g_abf[N_VEC * D_DIM];     // z rows, bf16(rn)
__device__ __nv_bfloat16      g_bbf[K_CODES * D_DIM];   // emb rows, bf16(rn)
__device__ float              g_zf [N_VEC * D_DIM];     // z rows, fp32 packed
__device__ float              g_sz [N_VEC];
__device__ unsigned int       g_rowmin[N_VEC];          // bits of min d1 (>0)
__device__ unsigned long long g_best[N_VEC];            // (bits(d)<<32)|k
__device__ __half             g_d1[(size_t)N_VEC * K_CODES]; // rd(d1-1), sparse
__device__ __half             g_blkmin[(size_t)N_VEC * N_TILES]; // tile mins
__device__ double             g_loss_part[256];

// ------------------------------ PTX helpers --------------------------------
__device__ __forceinline__ uint32_t smem_u32(const void* p) {
    uint32_t a;
    asm("{ .reg .u64 t; cvta.to.shared.u64 t, %1; cvt.u32.u64 %0, t; }"
        : "=r"(a) : "l"(p));
    return a;
}
__device__ __forceinline__ void ldm_x4(uint32_t* r, uint32_t addr) {
    asm volatile("ldmatrix.sync.aligned.m8n8.x4.shared.b16 {%0,%1,%2,%3}, [%4];"
                 : "=r"(r[0]), "=r"(r[1]), "=r"(r[2]), "=r"(r[3]) : "r"(addr));
}
__device__ __forceinline__ void mma_bf16(float* c, const uint32_t* a,
                                         uint32_t b0, uint32_t b1) {
    asm volatile(
        "mma.sync.aligned.m16n8k16.row.col.f32.bf16.bf16.f32 "
        "{%0,%1,%2,%3}, {%4,%5,%6,%7}, {%8,%9}, {%0,%1,%2,%3};"
        : "+f"(c[0]), "+f"(c[1]), "+f"(c[2]), "+f"(c[3])
        : "r"(a[0]), "r"(a[1]), "r"(a[2]), "r"(a[3]), "r"(b0), "r"(b1));
}

// ---------------------------------------------------------------------------
// pack z -> zf (fp32 row-major), abf (bf16), sz (sequential chain, identical
// order to the R1 kernel that verified rel_err 0.0)
// ---------------------------------------------------------------------------
__global__ void vq_pack_z_kernel(const float* __restrict__ z) {
    int n  = blockIdx.x * 64 + threadIdx.x;
    int b  = n >> 10;
    int hw = n & 1023;
    const float* zp = z + (size_t)b * 262144 + hw;
    float s = 0.f;
#pragma unroll 8
    for (int d = 0; d < D_DIM; d++) {
        float v = zp[(size_t)d * 1024];
        g_zf [n * D_DIM + d] = v;
        g_abf[n * D_DIM + d] = __float2bfloat16_rn(v);
        s = fmaf(v, v, s);
    }
    g_sz[n] = s;
}

// pack emb -> bf16; also folds the g_rowmin init (one fewer launch)
__global__ void vq_pack_e_kernel(const float* __restrict__ emb) {
    int gid = blockIdx.x * 256 + threadIdx.x;
    if (gid < N_VEC) g_rowmin[gid] = 0x7F800000u;   // +inf
    int i0 = blockIdx.x * 1024 + threadIdx.x;
#pragma unroll
    for (int j = 0; j < 4; j++) {
        int i = i0 + j * 256;
        g_bbf[i] = __float2bfloat16_rn(emb[i]);
    }
}

// ---------------------------------------------------------------------------
// SINGLE-PASS bf16 HMMA GEMM — verified R13/R14 mainloop: 128x128 tile,
// 8 warps of 32x64, 2 blk/SM, register-prefetch + double-buffered smem,
// one barrier per chunk.  Epilogue: d1 tile (fp16 rd) with conditional
// per-row stcs (skip rows that provably cannot qualify).
// ---------------------------------------------------------------------------
__global__ __launch_bounds__(256, 2)
void vq_mma_kernel() {
    __shared__ __align__(16) char s_raw[40960];
    __shared__ unsigned int s_tilemin[128];   // then reused as write-flag

    __nv_bfloat16 (*sA)[40] = reinterpret_cast<__nv_bfloat16(*)[40]>(s_raw);
    __nv_bfloat16 (*sB)[40] =
        reinterpret_cast<__nv_bfloat16(*)[40]>(s_raw + 20480);
    __half (*s_d1)[136] = reinterpret_cast<__half(*)[136]>(s_raw);

    const int tid  = threadIdx.x;
    const int lane = tid & 31;
    const int wid  = tid >> 5;
    const int wm   = wid >> 1;               // 0..3
    const int wn   = wid & 1;                // 0..1
    const int n0   = blockIdx.x * 128;       // z-row base
    const int k0   = blockIdx.y * 128;       // code base

    float acc[2][8][4];
#pragma unroll
    for (int mi = 0; mi < 2; mi++)
#pragma unroll
        for (int ni = 0; ni < 8; ni++)
#pragma unroll
            for (int r = 0; r < 4; r++) acc[mi][ni][r] = 0.f;

    if (tid < 128) s_tilemin[tid] = 0x7F800000u;

    const int lrow = tid >> 2;
    const int lq   = (tid & 3) * 8;

    const __nv_bfloat16* ap0 = &g_abf[(size_t)(n0 + lrow) * D_DIM + lq];
    const __nv_bfloat16* ap1 = ap0 + (size_t)64 * D_DIM;
    const __nv_bfloat16* bp0 = &g_bbf[(size_t)(k0 + lrow) * D_DIM + lq];
    const __nv_bfloat16* bp1 = bp0 + (size_t)64 * D_DIM;

    // prologue: chunk 0 -> buffer 0
    {
        uint4 a0 = *reinterpret_cast<const uint4*>(ap0);
        uint4 a1 = *reinterpret_cast<const uint4*>(ap1);
        uint4 b0 = *reinterpret_cast<const uint4*>(bp0);
        uint4 b1 = *reinterpret_cast<const uint4*>(bp1);
        *reinterpret_cast<uint4*>(&sA[lrow     ][lq]) = a0;
        *reinterpret_cast<uint4*>(&sA[lrow + 64][lq]) = a1;
        *reinterpret_cast<uint4*>(&sB[lrow     ][lq]) = b0;
        *reinterpret_cast<uint4*>(&sB[lrow + 64][lq]) = b1;
    }
    __syncthreads();

#pragma unroll
    for (int kc = 0; kc < 8; kc++) {
        const int cbuf = (kc & 1) * 128;
        const int nbuf = ((kc + 1) & 1) * 128;

        uint4 pa0, pa1, pb0, pb1;
        if (kc < 7) {
            const int kb = (kc + 1) * 32;
            pa0 = *reinterpret_cast<const uint4*>(ap0 + kb);
            pa1 = *reinterpret_cast<const uint4*>(ap1 + kb);
            pb0 = *reinterpret_cast<const uint4*>(bp0 + kb);
            pb1 = *reinterpret_cast<const uint4*>(bp1 + kb);
        }

#pragma unroll
        for (int ks = 0; ks < 2; ks++) {
            uint32_t a[2][4];
#pragma unroll
            for (int mi = 0; mi < 2; mi++) {
                int r = wm * 32 + mi * 16 + (lane & 15);
                int c = ks * 16 + (lane >> 4) * 8;
                ldm_x4(a[mi], smem_u32(&sA[cbuf + r][c]));
            }
            uint32_t b[4][4];
#pragma unroll
            for (int g = 0; g < 4; g++) {
                int r = wn * 64 + g * 16 + (lane & 15);
                int c = ks * 16 + (lane >> 4) * 8;
                ldm_x4(b[g], smem_u32(&sB[cbuf + r][c]));
            }
#pragma unroll
            for (int mi = 0; mi < 2; mi++)
#pragma unroll
                for (int g = 0; g < 4; g++) {
                    mma_bf16(acc[mi][2 * g],     a[mi], b[g][0], b[g][2]);
                    mma_bf16(acc[mi][2 * g + 1], a[mi], b[g][1], b[g][3]);
                }
        }

        if (kc < 7) {
            *reinterpret_cast<uint4*>(&sA[nbuf + lrow     ][lq]) = pa0;
            *reinterpret_cast<uint4*>(&sA[nbuf + lrow + 64][lq]) = pa1;
            *reinterpret_cast<uint4*>(&sB[nbuf + lrow     ][lq]) = pb0;
            *reinterpret_cast<uint4*>(&sB[nbuf + lrow + 64][lq]) = pb1;
        }
        __syncthreads();
    }

    // ---- epilogue: d1 tile -> smem (fp16 rd), per-row tile mins ----
#pragma unroll
    for (int mi = 0; mi < 2; mi++)
#pragma unroll
        for (int ci = 0; ci < 2; ci++) {
            int rl = wm * 32 + mi * 16 + ci * 8 + (lane >> 2);
            float mn = 3.402823466e+38f;
#pragma unroll
            for (int ni = 0; ni < 8; ni++) {
                float d0 = __fmaf_rn(-2.0f, acc[mi][ni][2 * ci],     1.0f);
                float d1 = __fmaf_rn(-2.0f, acc[mi][ni][2 * ci + 1], 1.0f);
                int col = wn * 64 + ni * 8 + (lane & 3) * 2;
                __half2 h = __halves2half2(
                    __float2half_rd(__fsub_rn(d0, 1.0f)),
                    __float2half_rd(__fsub_rn(d1, 1.0f)));
                *reinterpret_cast<__half2*>(&s_d1[rl][col]) = h;
                mn = fminf(mn, fminf(d0, d1));
            }
            mn = fminf(mn, __shfl_xor_sync(0xFFFFFFFFu, mn, 1));
            mn = fminf(mn, __shfl_xor_sync(0xFFFFFFFFu, mn, 2));
            if ((lane & 3) == 0)
                atomicMin(&s_tilemin[rl], __float_as_uint(mn));
        }
    __syncthreads();

    // per-row: rowmin exchange, tile-min index write, survivability flag
    unsigned int flag = 0;
    if (tid < 128) {
        unsigned int tm  = s_tilemin[tid];
        unsigned int old = atomicMin(&g_rowmin[n0 + tid], tm);
        unsigned int run = old < tm ? old : tm;     // running >= final rowmin
        __half hv = __float2half_rd(
            __fsub_rn(__uint_as_float(tm), 1.0f));
        g_blkmin[(size_t)(n0 + tid) * N_TILES + blockIdx.y] = hv;
        flag = (__half2float(hv) <=
                __uint_as_float(run) - 1.0f + MARGIN_D1) ? 1u : 0u;
    }
    __syncthreads();
    if (tid < 128) s_tilemin[tid] = flag;   // reuse as per-row write flag
    __syncthreads();

    // streaming store of the fp16 tile — ONLY rows that can still qualify
#pragma unroll
    for (int i = 0; i < 8; i++) {
        int idx = i * 256 + tid;             // 0..2047 (uint4 units)
        int row = idx >> 4;
        int col = (idx & 15) * 8;
        if (s_tilemin[row]) {
            float4 v = *reinterpret_cast<float4*>(&s_d1[row][col]);
            __stcs(reinterpret_cast<float4*>(
                &g_d1[(size_t)(n0 + row) * K_CODES + k0 + col]), v);
        }
    }
}

// ---------------------------------------------------------------------------
// Scan + exact rescore v3: one 128-thread block per z-row.
//  - stage 1: tile filter (256 B)
//  - stage 2: per-code filter in qualifying tiles
//  - stage 3: candidates rescored in batches of 8: all 128 threads stage the
//    8 emb rows into smem COALESCED (uint4), then 8 threads run the exact R1
//    sequential fmaf chain on the staged values (same fp32 bits, same order
//    -> bitwise-identical dval keys).
// ---------------------------------------------------------------------------
__global__ __launch_bounds__(128)
void vq_scan_rescore_kernel(const float* __restrict__ emb) {
    __shared__ float s_z[D_DIM];
    __shared__ __align__(16) float s_e[8][D_DIM];   // 8 staged emb rows
    __shared__ int   s_tlist[32];
    __shared__ int   s_tcnt;
    __shared__ int   s_list[512];
    __shared__ int   s_cnt;
    __shared__ unsigned long long s_best;

    const int n   = blockIdx.x;
    const int tid = threadIdx.x;

    if (tid == 0) { s_tcnt = 0; s_cnt = 0; s_best = 0xFFFFFFFFFFFFFFFFULL; }
    s_z[tid]       = g_zf[(size_t)n * D_DIM + tid];
    s_z[tid + 128] = g_zf[(size_t)n * D_DIM + tid + 128];
    const float thr = __uint_as_float(g_rowmin[n]) - 1.0f + MARGIN_D1;
    __syncthreads();

    // stage 1: tile filter (256 B)
    {
        float bm = __half2float(g_blkmin[(size_t)n * N_TILES + tid]);
        if (bm <= thr) {
            int p = atomicAdd(&s_tcnt, 1);
            if (p < 32) s_tlist[p] = tid;
        }
    }
    __syncthreads();

    // stage 2: per-code filter within qualifying tiles (uint2 = 4 halves)
    int tc = s_tcnt < 32 ? s_tcnt : 32;
    for (int t = 0; t < tc; t++) {
        int kb = s_tlist[t] * 128;
        if (tid < 32) {
            uint2 v = __ldcs(reinterpret_cast<const uint2*>(
                &g_d1[(size_t)n * K_CODES + kb + tid * 4]));
            __half2 p0 = *reinterpret_cast<__half2*>(&v.x);
            __half2 p1 = *reinterpret_cast<__half2*>(&v.y);
            float m0 = __low2float(p0), m1 = __high2float(p0);
            float m2 = __low2float(p1), m3 = __high2float(p1);
            int kbase = kb + tid * 4;
            if (m0 <= thr) { int p = atomicAdd(&s_cnt, 1); if (p < 512) s_list[p] = kbase + 0; }
            if (m1 <= thr) { int p = atomicAdd(&s_cnt, 1); if (p < 512) s_list[p] = kbase + 1; }
            if (m2 <= thr) { int p = atomicAdd(&s_cnt, 1); if (p < 512) s_list[p] = kbase + 2; }
            if (m3 <= thr) { int p = atomicAdd(&s_cnt, 1); if (p < 512) s_list[p] = kbase + 3; }
        }
    }
    __syncthreads();

    // stage 3: batched smem-staged exact rescore
    int cnt = s_cnt < 512 ? s_cnt : 512;
    float sz = g_sz[n];
    for (int base = 0; base < cnt; base += 8) {
        int nb = cnt - base;
        if (nb > 8) nb = 8;
        // coalesced staging: nb rows x 64 uint4
        for (int u = tid; u < nb * 64; u += 128) {
            int r = u >> 6;
            int q = u & 63;
            *reinterpret_cast<uint4*>(&s_e[r][q * 4]) =
                *reinterpret_cast<const uint4*>(
                    &emb[(size_t)s_list[base + r] * D_DIM + q * 4]);
        }
        __syncthreads();
        if (tid < nb) {
            int k = s_list[base + tid];
            float acc = 0.f;
#pragma unroll 8
            for (int d = 0; d < D_DIM; d++)
                acc = fmaf(s_z[d], s_e[tid][d], acc);   // exact R1 chain
            float dval = __fsub_rn(sz, __fmul_rn(2.0f, acc));
            unsigned long long key =
                ((unsigned long long)__float_as_uint(dval) << 32) |
                (unsigned int)k;
            atomicMin(&s_best, key);
        }
        __syncthreads();
    }
    if (tid == 0) g_best[n] = s_best;
}

// ---------------------------------------------------------------------------
// finalize: 256 blocks = (32 n-groups) x (8 d-chunks); verified R1 math.
// ---------------------------------------------------------------------------
__global__ void vq_finalize_kernel(const float* __restrict__ z,
                                   const float* __restrict__ emb,
                                   float* __restrict__ out, int out_size) {
    __shared__ double sred[256];
    int ng = blockIdx.x >> 3;
    int dc = blockIdx.x & 7;
    int n  = ng * 256 + threadIdx.x;
    int b  = n >> 10;
    int hw = n & 1023;

    int k = (int)(unsigned int)(g_best[n] & 0xFFFFFFFFu);

    const float* e  = emb + (size_t)k * D_DIM;
    const float* zp = z   + (size_t)b * 262144 + hw;
    float*       op = out + (size_t)b * 262144 + hw;

    double lsum = 0.0;
#pragma unroll 8
    for (int d = dc * 32; d < dc * 32 + 32; d++) {
        float zv   = zp[(size_t)d * 1024];
        float ev   = e[d];
        float diff = __fsub_rn(ev, zv);          // fl(z_q - z)
        float q    = __fadd_rn(zv, diff);        // fl(z + fl(z_q - z))
        op[(size_t)d * 1024] = q;
        lsum += (double)diff * (double)diff;
    }

    if (dc == 0) {
        int idx_pos = 2097152 + 1 + n;
        if (idx_pos < out_size) out[idx_pos] = (float)k;
    }

    sred[threadIdx.x] = lsum;
    __syncthreads();
    for (int s = 128; s > 0; s >>= 1) {
        if (threadIdx.x < s) sred[threadIdx.x] += sred[threadIdx.x + s];
        __syncthreads();
    }
    if (threadIdx.x == 0) g_loss_part[blockIdx.x] = sred[0];
}

__global__ void vq_loss_kernel(float* __restrict__ out, int out_size) {
    if (threadIdx.x == 0 && blockIdx.x == 0) {
        double s = 0.0;
        for (int i = 0; i < 256; i++) s += g_loss_part[i];
        double mean = s / 2097152.0;
        if (2097152 < out_size) out[2097152] = (float)(mean * 1.25);
    }
}

// ---------------------------------------------------------------------------
extern "C" void kernel_launch(void* const* d_in, const int* in_sizes, int n_in,
                              void* d_out, int out_size) {
    const float* z   = (const float*)d_in[0];   // [8,256,32,32]
    const float* emb = (const float*)d_in[1];   // [16384,256]
    float* out = (float*)d_out;

    vq_pack_z_kernel<<<128, 64>>>(z);
    vq_pack_e_kernel<<<4096, 256>>>(emb);       // also inits g_rowmin

    dim3 grid(N_VEC / 128, K_CODES / 128);     // 64 x 128 = 8192 blocks
    vq_mma_kernel<<<grid, 256>>>();

    vq_scan_rescore_kernel<<<N_VEC, 128>>>(emb);
    vq_finalize_kernel<<<256, 256>>>(z, emb, out, out_size);
    vq_loss_kernel<<<1, 32>>>(out, out_size);
}